// round 1
// baseline (speedup 1.0000x reference)
#include <cuda_runtime.h>
#include <cuda_bf16.h>
#include <math.h>

// Problem dims (fixed)
#define BB 4
#define TT 2048
#define CC 1024
#define HH 16
#define DD 64
#define MROWS (BB*TT)          // 8192

// Scratch (device globals; cudaMalloc is banned)
__device__ float g_Q[MROWS*CC];
__device__ float g_K[MROWS*CC];
__device__ float g_V[MROWS*CC];
__device__ float g_G[MROWS*CC];
__device__ float g_OG[MROWS*CC];
__device__ float g_Beta[MROWS*HH];

// ---------------------------------------------------------------------------
// Tiled SGEMM: C[M,N] = A[M,K] @ B[N,K]^T   (both row-major, K-major inner)
// BM=BN=128, BK=16, 256 threads, 8x8 per thread.
// MODE 0: plain store. MODE 1: sigmoid store.
// Assumes M%128==0, N%128==0, K%16==0 (true here).
// ---------------------------------------------------------------------------
template<int MODE>
__global__ __launch_bounds__(256, 2)
void sgemm_kernel(const float* __restrict__ A, const float* __restrict__ Bw,
                  float* __restrict__ Cc, int Mdim, int Ndim, int Kdim)
{
    __shared__ float As[16][128];
    __shared__ float Bs[16][128];

    const int tid = threadIdx.x;
    const int m0 = blockIdx.y * 128;
    const int n0 = blockIdx.x * 128;
    const int ty = tid >> 4;   // 0..15
    const int tx = tid & 15;   // 0..15

    float acc[8][8];
#pragma unroll
    for (int i = 0; i < 8; i++)
#pragma unroll
        for (int j = 0; j < 8; j++) acc[i][j] = 0.0f;

    // load indices: 512 float4s per tile per matrix -> 2 per thread
    const int la_m0 = (tid + 0)   >> 2;           // 0..63  (first half rows? no: 0..127 over both)
    const int la_k0 = ((tid + 0)  & 3) * 4;
    const int la_m1 = (tid + 256) >> 2;
    const int la_k1 = ((tid + 256) & 3) * 4;

    for (int k0 = 0; k0 < Kdim; k0 += 16) {
        // global loads into registers
        float4 a0 = *(const float4*)&A[(size_t)(m0 + la_m0) * Kdim + k0 + la_k0];
        float4 a1 = *(const float4*)&A[(size_t)(m0 + la_m1) * Kdim + k0 + la_k1];
        float4 b0 = *(const float4*)&Bw[(size_t)(n0 + la_m0) * Kdim + k0 + la_k0];
        float4 b1 = *(const float4*)&Bw[(size_t)(n0 + la_m1) * Kdim + k0 + la_k1];

        __syncthreads();   // previous compute done before smem overwrite
        As[la_k0 + 0][la_m0] = a0.x; As[la_k0 + 1][la_m0] = a0.y;
        As[la_k0 + 2][la_m0] = a0.z; As[la_k0 + 3][la_m0] = a0.w;
        As[la_k1 + 0][la_m1] = a1.x; As[la_k1 + 1][la_m1] = a1.y;
        As[la_k1 + 2][la_m1] = a1.z; As[la_k1 + 3][la_m1] = a1.w;
        Bs[la_k0 + 0][la_m0] = b0.x; Bs[la_k0 + 1][la_m0] = b0.y;
        Bs[la_k0 + 2][la_m0] = b0.z; Bs[la_k0 + 3][la_m0] = b0.w;
        Bs[la_k1 + 0][la_m1] = b1.x; Bs[la_k1 + 1][la_m1] = b1.y;
        Bs[la_k1 + 2][la_m1] = b1.z; Bs[la_k1 + 3][la_m1] = b1.w;
        __syncthreads();

#pragma unroll
        for (int k = 0; k < 16; k++) {
            float4 ra0 = *(const float4*)&As[k][ty * 8];
            float4 ra1 = *(const float4*)&As[k][ty * 8 + 4];
            float4 rb0 = *(const float4*)&Bs[k][tx * 8];
            float4 rb1 = *(const float4*)&Bs[k][tx * 8 + 4];
            float ra[8] = {ra0.x, ra0.y, ra0.z, ra0.w, ra1.x, ra1.y, ra1.z, ra1.w};
            float rb[8] = {rb0.x, rb0.y, rb0.z, rb0.w, rb1.x, rb1.y, rb1.z, rb1.w};
#pragma unroll
            for (int i = 0; i < 8; i++)
#pragma unroll
                for (int j = 0; j < 8; j++)
                    acc[i][j] = fmaf(ra[i], rb[j], acc[i][j]);
        }
    }

    // epilogue
#pragma unroll
    for (int i = 0; i < 8; i++) {
        float* crow = &Cc[(size_t)(m0 + ty * 8 + i) * Ndim + n0 + tx * 8];
#pragma unroll
        for (int j = 0; j < 8; j++) {
            float v = acc[i][j];
            if (MODE == 1) v = 1.0f / (1.0f + expf(-v));
            crow[j] = v;
        }
    }
}

// ---------------------------------------------------------------------------
// beta = sigmoid(x @ Wbeta^T + bbeta) : (8192, 16)
// one block per token row, 16 warps (one per head)
// ---------------------------------------------------------------------------
__global__ __launch_bounds__(512)
void beta_kernel(const float* __restrict__ x, const float* __restrict__ Wb,
                 const float* __restrict__ bb, float* __restrict__ Beta)
{
    __shared__ float xs[CC];
    const int row = blockIdx.x;
    const int tid = threadIdx.x;
    for (int i = tid; i < CC; i += 512) xs[i] = x[(size_t)row * CC + i];
    __syncthreads();

    const int h = tid >> 5;
    const int lane = tid & 31;
    const float* wrow = &Wb[(size_t)h * CC];
    float acc = 0.0f;
#pragma unroll 8
    for (int c = lane; c < CC; c += 32) acc = fmaf(xs[c], wrow[c], acc);
#pragma unroll
    for (int off = 16; off > 0; off >>= 1)
        acc += __shfl_xor_sync(0xffffffffu, acc, off);
    if (lane == 0) {
        float v = acc + bb[h];
        Beta[(size_t)row * HH + h] = 1.0f / (1.0f + expf(-v));
    }
}

// ---------------------------------------------------------------------------
// L2-normalize Q and K per (row, head) over D=64.  one warp per (row,head,which)
// ---------------------------------------------------------------------------
__global__ __launch_bounds__(256)
void norm_kernel()
{
    const int gw = blockIdx.x * 8 + (threadIdx.x >> 5);  // 0 .. 2*MROWS*HH-1
    const int lane = threadIdx.x & 31;
    const int which = gw & 1;
    const int rem = gw >> 1;
    const int row = rem >> 4;
    const int h = rem & 15;
    float* P = which ? g_K : g_Q;
    float* p = &P[(size_t)row * CC + h * DD];
    float v0 = p[lane];
    float v1 = p[lane + 32];
    float s = v0 * v0 + v1 * v1;
#pragma unroll
    for (int off = 16; off > 0; off >>= 1)
        s += __shfl_xor_sync(0xffffffffu, s, off);
    float n = sqrtf(s);
    float scale = 1.0f / fmaxf(n, 1e-12f);
    p[lane]      = v0 * scale;
    p[lane + 32] = v1 * scale;
}

// ---------------------------------------------------------------------------
// Delta-rule scan. One block per (b,h). 256 threads.
// Thread t: d = t>>2 owns row d of M; cg = t&3 owns columns [cg*16, cg*16+16).
// Per step: o = M q (pre-update), dv = v - M k, M += beta * dv k^T.
// Writes g_OG = gate * o (fused).
// ---------------------------------------------------------------------------
__global__ __launch_bounds__(256, 1)
void scan_kernel()
{
    const int b = blockIdx.x >> 4;
    const int h = blockIdx.x & 15;
    __shared__ float sq[DD], sk[DD], sv[DD], sg[DD];
    __shared__ float sb;

    const int t = threadIdx.x;
    const int d = t >> 2;
    const int cg = t & 3;
    const int cbase = cg * 16;

    float Mreg[16];
#pragma unroll
    for (int j = 0; j < 16; j++) Mreg[j] = 0.0f;

    for (int step = 0; step < TT; step++) {
        const size_t r = (size_t)b * TT + step;
        const size_t base = r * CC + h * DD;
        if (t < 64)        sq[t]       = g_Q[base + t];
        else if (t < 128)  sk[t - 64]  = g_K[base + t - 64];
        else if (t < 192)  sv[t - 128] = g_V[base + t - 128];
        else               sg[t - 192] = g_G[base + t - 192];
        if (t == 0) sb = g_Beta[r * HH + h];
        __syncthreads();

        float po = 0.0f, pk = 0.0f;
#pragma unroll
        for (int j = 0; j < 16; j++) {
            float m = Mreg[j];
            po = fmaf(m, sq[cbase + j], po);
            pk = fmaf(m, sk[cbase + j], pk);
        }
        // reduce over the 4-thread column group (lanes 4g..4g+3)
        po += __shfl_xor_sync(0xffffffffu, po, 1);
        po += __shfl_xor_sync(0xffffffffu, po, 2);
        pk += __shfl_xor_sync(0xffffffffu, pk, 1);
        pk += __shfl_xor_sync(0xffffffffu, pk, 2);

        const float dv = sv[d] - pk;
        const float bdv = sb * dv;
#pragma unroll
        for (int j = 0; j < 16; j++)
            Mreg[j] = fmaf(bdv, sk[cbase + j], Mreg[j]);

        if (cg == 0) g_OG[base + d] = sg[d] * po;
        __syncthreads();
    }
}

// ---------------------------------------------------------------------------
extern "C" void kernel_launch(void* const* d_in, const int* in_sizes, int n_in,
                              void* d_out, int out_size)
{
    const float* x     = (const float*)d_in[0];
    const float* Wq    = (const float*)d_in[1];
    const float* Wk    = (const float*)d_in[2];
    const float* Wv    = (const float*)d_in[3];
    const float* Wbeta = (const float*)d_in[4];
    const float* bbeta = (const float*)d_in[5];
    const float* Wgate = (const float*)d_in[6];
    const float* Wo    = (const float*)d_in[7];
    float* out = (float*)d_out;

    float *Qp, *Kp, *Vp, *Gp, *OGp, *Bp;
    cudaGetSymbolAddress((void**)&Qp,  g_Q);
    cudaGetSymbolAddress((void**)&Kp,  g_K);
    cudaGetSymbolAddress((void**)&Vp,  g_V);
    cudaGetSymbolAddress((void**)&Gp,  g_G);
    cudaGetSymbolAddress((void**)&OGp, g_OG);
    cudaGetSymbolAddress((void**)&Bp,  g_Beta);

    dim3 ggrid(CC / 128, MROWS / 128);

    sgemm_kernel<0><<<ggrid, 256>>>(x, Wq,    Qp, MROWS, CC, CC);
    sgemm_kernel<0><<<ggrid, 256>>>(x, Wk,    Kp, MROWS, CC, CC);
    sgemm_kernel<0><<<ggrid, 256>>>(x, Wv,    Vp, MROWS, CC, CC);
    sgemm_kernel<1><<<ggrid, 256>>>(x, Wgate, Gp, MROWS, CC, CC);
    beta_kernel<<<MROWS, 512>>>(x, Wbeta, bbeta, Bp);
    norm_kernel<<<(2 * MROWS * HH) / 8, 256>>>();
    scan_kernel<<<BB * HH, 256>>>();
    sgemm_kernel<0><<<ggrid, 256>>>(OGp, Wo, out, MROWS, CC, CC);
}

// round 2
// speedup vs baseline: 1.2972x; 1.2972x over previous
#include <cuda_runtime.h>
#include <cuda_bf16.h>
#include <math.h>

// Problem dims (fixed)
#define BB 4
#define TT 2048
#define CC 1024
#define HH 16
#define DD 64
#define MROWS (BB*TT)          // 8192

// Scratch (device globals; cudaMalloc is banned)
__device__ float g_Q[MROWS*CC];
__device__ float g_K[MROWS*CC];
__device__ float g_V[MROWS*CC];
__device__ float g_G[MROWS*CC];
__device__ float g_OG[MROWS*CC];
__device__ float g_Beta[MROWS*HH];

// ---------------------------------------------------------------------------
// Tiled SGEMM: C[M,N] = A[M,K] @ B[N,K]^T   (row-major, K-major inner dim)
// BM=BN=128, BK=16, 256 threads, 8x8 per thread, double-buffered smem,
// ONE __syncthreads per K-chunk.
// MODE 0: plain store. MODE 1: sigmoid store.
// ---------------------------------------------------------------------------
template<int MODE>
__global__ __launch_bounds__(256, 2)
void sgemm_kernel(const float* __restrict__ A, const float* __restrict__ Bw,
                  float* __restrict__ Cc, int Kdim, int Ndim)
{
    __shared__ float As[2][16][128];
    __shared__ float Bs[2][16][128];

    const int tid = threadIdx.x;
    const int m0 = blockIdx.y * 128;
    const int n0 = blockIdx.x * 128;
    const int ty = tid >> 4;   // 0..15
    const int tx = tid & 15;   // 0..15

    // loader mapping: 1024 floats per matrix per chunk = 256 float4
    // thread loads rows lm and lm+64, 4 consecutive k each
    const int lm  = tid >> 2;          // 0..63
    const int lm2 = lm + 64;           // 64..127
    const int lk  = (tid & 3) * 4;     // 0,4,8,12

    float acc[8][8];
#pragma unroll
    for (int i = 0; i < 8; i++)
#pragma unroll
        for (int j = 0; j < 8; j++) acc[i][j] = 0.0f;

    const float* Arow0 = &A[(size_t)(m0 + lm)  * Kdim + lk];
    const float* Arow1 = &A[(size_t)(m0 + lm2) * Kdim + lk];
    const float* Brow0 = &Bw[(size_t)(n0 + lm)  * Kdim + lk];
    const float* Brow1 = &Bw[(size_t)(n0 + lm2) * Kdim + lk];

    // preload chunk 0
    float4 a0 = *(const float4*)Arow0;
    float4 a1 = *(const float4*)Arow1;
    float4 b0 = *(const float4*)Brow0;
    float4 b1 = *(const float4*)Brow1;
    As[0][lk+0][lm]  = a0.x; As[0][lk+1][lm]  = a0.y; As[0][lk+2][lm]  = a0.z; As[0][lk+3][lm]  = a0.w;
    As[0][lk+0][lm2] = a1.x; As[0][lk+1][lm2] = a1.y; As[0][lk+2][lm2] = a1.z; As[0][lk+3][lm2] = a1.w;
    Bs[0][lk+0][lm]  = b0.x; Bs[0][lk+1][lm]  = b0.y; Bs[0][lk+2][lm]  = b0.z; Bs[0][lk+3][lm]  = b0.w;
    Bs[0][lk+0][lm2] = b1.x; Bs[0][lk+1][lm2] = b1.y; Bs[0][lk+2][lm2] = b1.z; Bs[0][lk+3][lm2] = b1.w;
    __syncthreads();

    const int nk = Kdim >> 4;
    for (int kt = 0; kt < nk; kt++) {
        const int buf = kt & 1;
        // issue global loads for next chunk (hidden under compute)
        if (kt + 1 < nk) {
            const int off = (kt + 1) * 16;
            a0 = *(const float4*)(Arow0 + off);
            a1 = *(const float4*)(Arow1 + off);
            b0 = *(const float4*)(Brow0 + off);
            b1 = *(const float4*)(Brow1 + off);
        }

#pragma unroll
        for (int k = 0; k < 16; k++) {
            float4 ra0 = *(const float4*)&As[buf][k][ty * 8];
            float4 ra1 = *(const float4*)&As[buf][k][ty * 8 + 4];
            float4 rb0 = *(const float4*)&Bs[buf][k][tx * 8];
            float4 rb1 = *(const float4*)&Bs[buf][k][tx * 8 + 4];
            float ra[8] = {ra0.x, ra0.y, ra0.z, ra0.w, ra1.x, ra1.y, ra1.z, ra1.w};
            float rb[8] = {rb0.x, rb0.y, rb0.z, rb0.w, rb1.x, rb1.y, rb1.z, rb1.w};
#pragma unroll
            for (int i = 0; i < 8; i++)
#pragma unroll
                for (int j = 0; j < 8; j++)
                    acc[i][j] = fmaf(ra[i], rb[j], acc[i][j]);
        }

        if (kt + 1 < nk) {
            const int nb = buf ^ 1;
            As[nb][lk+0][lm]  = a0.x; As[nb][lk+1][lm]  = a0.y; As[nb][lk+2][lm]  = a0.z; As[nb][lk+3][lm]  = a0.w;
            As[nb][lk+0][lm2] = a1.x; As[nb][lk+1][lm2] = a1.y; As[nb][lk+2][lm2] = a1.z; As[nb][lk+3][lm2] = a1.w;
            Bs[nb][lk+0][lm]  = b0.x; Bs[nb][lk+1][lm]  = b0.y; Bs[nb][lk+2][lm]  = b0.z; Bs[nb][lk+3][lm]  = b0.w;
            Bs[nb][lk+0][lm2] = b1.x; Bs[nb][lk+1][lm2] = b1.y; Bs[nb][lk+2][lm2] = b1.z; Bs[nb][lk+3][lm2] = b1.w;
        }
        __syncthreads();
    }

    // epilogue
#pragma unroll
    for (int i = 0; i < 8; i++) {
        float* crow = &Cc[(size_t)(m0 + ty * 8 + i) * Ndim + n0 + tx * 8];
#pragma unroll
        for (int j = 0; j < 8; j++) {
            float v = acc[i][j];
            if (MODE == 1) v = 1.0f / (1.0f + expf(-v));
            crow[j] = v;
        }
    }
}

// ---------------------------------------------------------------------------
// beta = sigmoid(x @ Wbeta^T + bbeta) : (8192, 16)
// ---------------------------------------------------------------------------
__global__ __launch_bounds__(512)
void beta_kernel(const float* __restrict__ x, const float* __restrict__ Wb,
                 const float* __restrict__ bb, float* __restrict__ Beta)
{
    __shared__ float xs[CC];
    const int row = blockIdx.x;
    const int tid = threadIdx.x;
    for (int i = tid; i < CC; i += 512) xs[i] = x[(size_t)row * CC + i];
    __syncthreads();

    const int h = tid >> 5;
    const int lane = tid & 31;
    const float* wrow = &Wb[(size_t)h * CC];
    float acc = 0.0f;
#pragma unroll 8
    for (int c = lane; c < CC; c += 32) acc = fmaf(xs[c], wrow[c], acc);
#pragma unroll
    for (int off = 16; off > 0; off >>= 1)
        acc += __shfl_xor_sync(0xffffffffu, acc, off);
    if (lane == 0) {
        float v = acc + bb[h];
        Beta[(size_t)row * HH + h] = 1.0f / (1.0f + expf(-v));
    }
}

// ---------------------------------------------------------------------------
// L2-normalize Q and K per (row, head) over D=64.  one warp per (row,head,which)
// ---------------------------------------------------------------------------
__global__ __launch_bounds__(256)
void norm_kernel()
{
    const int gw = blockIdx.x * 8 + (threadIdx.x >> 5);
    const int lane = threadIdx.x & 31;
    const int which = gw & 1;
    const int rem = gw >> 1;
    const int row = rem >> 4;
    const int h = rem & 15;
    float* P = which ? g_K : g_Q;
    float* p = &P[(size_t)row * CC + h * DD];
    float v0 = p[lane];
    float v1 = p[lane + 32];
    float s = v0 * v0 + v1 * v1;
#pragma unroll
    for (int off = 16; off > 0; off >>= 1)
        s += __shfl_xor_sync(0xffffffffu, s, off);
    float n = sqrtf(s);
    float scale = 1.0f / fmaxf(n, 1e-12f);
    p[lane]      = v0 * scale;
    p[lane + 32] = v1 * scale;
}

// ---------------------------------------------------------------------------
// Delta-rule scan. One block per (b,h). 256 threads.
// Thread t: d = t>>2 owns row d of M; cg = t&3 owns 16 columns.
// Software-pipelined: depth-2 register prefetch, double-buffered smem,
// ONE __syncthreads per step.
// Writes g_OG = gate * o (fused).
// ---------------------------------------------------------------------------
__global__ __launch_bounds__(256, 1)
void scan_kernel()
{
    const int b = blockIdx.x >> 4;
    const int h = blockIdx.x & 15;
    // layout per buffer: [0:64)=q [64:128)=k [128:192)=v [192:256)=g
    __shared__ float s[2][256];
    __shared__ float sbv[2];

    const int t = threadIdx.x;
    const int d = t >> 2;
    const int cg = t & 3;
    const int cbase = cg * 16;

    // which element this thread fetches each step
    const int arr = t >> 6;        // 0=q 1=k 2=v 3=g
    const int idx = t & 63;
    const float* src = (arr == 0) ? g_Q : (arr == 1) ? g_K : (arr == 2) ? g_V : g_G;

    const size_t rbase = (size_t)b * TT;

    float Mreg[16];
#pragma unroll
    for (int j = 0; j < 16; j++) Mreg[j] = 0.0f;

    // prefetch steps 0 and 1
    float p0 = src[(rbase + 0) * CC + h * DD + idx];
    float p1 = src[(rbase + 1) * CC + h * DD + idx];
    float pb0 = 0.0f, pb1 = 0.0f;
    if (t == 0) {
        pb0 = g_Beta[(rbase + 0) * HH + h];
        pb1 = g_Beta[(rbase + 1) * HH + h];
    }
    s[0][t] = p0;
    if (t == 0) sbv[0] = pb0;
    __syncthreads();

    for (int step = 0; step < TT; step++) {
        const int buf = step & 1;

        // issue prefetch for step+2 (consumed two iterations from now)
        float pn = 0.0f, pbn = 0.0f;
        if (step + 2 < TT) {
            pn = src[(rbase + step + 2) * CC + h * DD + idx];
            if (t == 0) pbn = g_Beta[(rbase + step + 2) * HH + h];
        }

        const float* sq = &s[buf][0];
        const float* sk = &s[buf][64];
        const float* sv = &s[buf][128];
        const float* sg = &s[buf][192];
        const float sb = sbv[buf];

        float po = 0.0f, pk = 0.0f;
#pragma unroll
        for (int j = 0; j < 16; j++) {
            float m = Mreg[j];
            po = fmaf(m, sq[cbase + j], po);
            pk = fmaf(m, sk[cbase + j], pk);
        }
        po += __shfl_xor_sync(0xffffffffu, po, 1);
        po += __shfl_xor_sync(0xffffffffu, po, 2);
        pk += __shfl_xor_sync(0xffffffffu, pk, 1);
        pk += __shfl_xor_sync(0xffffffffu, pk, 2);

        const float dv = sv[d] - pk;
        const float bdv = sb * dv;
#pragma unroll
        for (int j = 0; j < 16; j++)
            Mreg[j] = fmaf(bdv, sk[cbase + j], Mreg[j]);

        if (cg == 0)
            g_OG[(rbase + step) * CC + h * DD + d] = sg[d] * po;

        // stage data for step+1 into the other buffer
        if (step + 1 < TT) {
            s[buf ^ 1][t] = p1;
            if (t == 0) sbv[buf ^ 1] = pb1;
        }
        p1 = pn; pb1 = pbn;
        __syncthreads();
    }
}

// ---------------------------------------------------------------------------
extern "C" void kernel_launch(void* const* d_in, const int* in_sizes, int n_in,
                              void* d_out, int out_size)
{
    const float* x     = (const float*)d_in[0];
    const float* Wq    = (const float*)d_in[1];
    const float* Wk    = (const float*)d_in[2];
    const float* Wv    = (const float*)d_in[3];
    const float* Wbeta = (const float*)d_in[4];
    const float* bbeta = (const float*)d_in[5];
    const float* Wgate = (const float*)d_in[6];
    const float* Wo    = (const float*)d_in[7];
    float* out = (float*)d_out;

    float *Qp, *Kp, *Vp, *Gp, *OGp, *Bp;
    cudaGetSymbolAddress((void**)&Qp,  g_Q);
    cudaGetSymbolAddress((void**)&Kp,  g_K);
    cudaGetSymbolAddress((void**)&Vp,  g_V);
    cudaGetSymbolAddress((void**)&Gp,  g_G);
    cudaGetSymbolAddress((void**)&OGp, g_OG);
    cudaGetSymbolAddress((void**)&Bp,  g_Beta);

    dim3 ggrid(CC / 128, MROWS / 128);

    sgemm_kernel<0><<<ggrid, 256>>>(x, Wq,    Qp, CC, CC);
    sgemm_kernel<0><<<ggrid, 256>>>(x, Wk,    Kp, CC, CC);
    sgemm_kernel<0><<<ggrid, 256>>>(x, Wv,    Vp, CC, CC);
    sgemm_kernel<1><<<ggrid, 256>>>(x, Wgate, Gp, CC, CC);
    beta_kernel<<<MROWS, 512>>>(x, Wbeta, bbeta, Bp);
    norm_kernel<<<(2 * MROWS * HH) / 8, 256>>>();
    scan_kernel<<<BB * HH, 256>>>();
    sgemm_kernel<0><<<ggrid, 256>>>(OGp, Wo, out, CC, CC);
}

// round 5
// speedup vs baseline: 2.8101x; 2.1663x over previous
#include <cuda_runtime.h>
#include <cuda_bf16.h>
#include <math.h>
#include <stdint.h>

// Problem dims (fixed)
#define BB 4
#define TT 2048
#define CC 1024
#define HH 16
#define DD 64
#define MROWS (BB*TT)          // 8192

// ---------------------------------------------------------------------------
// Device scratch (cudaMalloc banned)
// ---------------------------------------------------------------------------
__device__ float g_Q[MROWS*CC];
__device__ float g_K[MROWS*CC];
__device__ float g_V[MROWS*CC];
__device__ float g_G[MROWS*CC];
__device__ float g_OG[MROWS*CC];
__device__ float g_Beta[MROWS*HH];

__device__ __nv_bfloat16 g_xhi[MROWS*CC];
__device__ __nv_bfloat16 g_xlo[MROWS*CC];
__device__ __nv_bfloat16 g_whi[5*CC*CC];
__device__ __nv_bfloat16 g_wlo[5*CC*CC];
__device__ __nv_bfloat16 g_oghi[MROWS*CC];
__device__ __nv_bfloat16 g_oglo[MROWS*CC];

// ---------------------------------------------------------------------------
// PTX helpers (base-ISA only: mma.sync / ldmatrix / cp.async)
// ---------------------------------------------------------------------------
__device__ __forceinline__ uint32_t smem_u32(const void* p) {
    uint32_t a;
    asm("{ .reg .u64 t; cvta.to.shared.u64 t, %1; cvt.u32.u64 %0, t; }" : "=r"(a) : "l"(p));
    return a;
}
__device__ __forceinline__ void cp16(uint32_t dst, const void* src) {
    asm volatile("cp.async.cg.shared.global [%0], [%1], 16;" :: "r"(dst), "l"(src));
}
#define CP_COMMIT() asm volatile("cp.async.commit_group;" ::: "memory")
#define CP_WAIT1()  asm volatile("cp.async.wait_group 1;" ::: "memory")
#define CP_WAIT0()  asm volatile("cp.async.wait_group 0;" ::: "memory")

__device__ __forceinline__ void ldm_x4(uint32_t* r, uint32_t addr) {
    asm volatile("ldmatrix.sync.aligned.m8n8.x4.shared.b16 {%0,%1,%2,%3}, [%4];"
        : "=r"(r[0]), "=r"(r[1]), "=r"(r[2]), "=r"(r[3]) : "r"(addr));
}
__device__ __forceinline__ void mma16816(float* d, const uint32_t* a, const uint32_t* b) {
    asm volatile("mma.sync.aligned.m16n8k16.row.col.f32.bf16.bf16.f32 "
        "{%0,%1,%2,%3}, {%4,%5,%6,%7}, {%8,%9}, {%0,%1,%2,%3};"
        : "+f"(d[0]), "+f"(d[1]), "+f"(d[2]), "+f"(d[3])
        : "r"(a[0]), "r"(a[1]), "r"(a[2]), "r"(a[3]), "r"(b[0]), "r"(b[1]));
}

// ---------------------------------------------------------------------------
// fp32 -> (bf16 hi, bf16 lo) split conversion, float4-vectorized
// ---------------------------------------------------------------------------
__global__ __launch_bounds__(256)
void conv_hl_kernel(const float* __restrict__ in, __nv_bfloat16* __restrict__ hi,
                    __nv_bfloat16* __restrict__ lo)
{
    const int i = blockIdx.x * 256 + threadIdx.x;   // float4 index
    float4 v = ((const float4*)in)[i];
    __nv_bfloat16 h0 = __float2bfloat16(v.x);
    __nv_bfloat16 h1 = __float2bfloat16(v.y);
    __nv_bfloat16 h2 = __float2bfloat16(v.z);
    __nv_bfloat16 h3 = __float2bfloat16(v.w);
    __nv_bfloat16 l0 = __float2bfloat16(v.x - __bfloat162float(h0));
    __nv_bfloat16 l1 = __float2bfloat16(v.y - __bfloat162float(h1));
    __nv_bfloat16 l2 = __float2bfloat16(v.z - __bfloat162float(h2));
    __nv_bfloat16 l3 = __float2bfloat16(v.w - __bfloat162float(h3));
    ushort4 hv = { __bfloat16_as_ushort(h0), __bfloat16_as_ushort(h1),
                   __bfloat16_as_ushort(h2), __bfloat16_as_ushort(h3) };
    ushort4 lv = { __bfloat16_as_ushort(l0), __bfloat16_as_ushort(l1),
                   __bfloat16_as_ushort(l2), __bfloat16_as_ushort(l3) };
    ((ushort4*)hi)[i] = hv;
    ((ushort4*)lo)[i] = lv;
}

// ---------------------------------------------------------------------------
// HMMA split-bf16 GEMM: C[8192,1024] = A[8192,1024] @ B[1024,1024]^T
//   C = Ahi*Bhi + Ahi*Blo + Alo*Bhi  (fp32 accum)
// CTA tile 128x128, BK=64, 8 warps (2x4), warp tile 64x32.
// cp.async double-buffered smem, XOR-swizzled rows (conflict-free ldmatrix).
// MODE 1: sigmoid on store.
// ---------------------------------------------------------------------------
#define ST_BYTES 65536          // per stage: 4 matrices x 128x64 bf16 (16KB each)
#define GEMM_SMEM (2*ST_BYTES)  // 128 KB

template<int MODE>
__global__ __launch_bounds__(256, 1)
void mma_gemm(const __nv_bfloat16* __restrict__ Ahi, const __nv_bfloat16* __restrict__ Alo,
              const __nv_bfloat16* __restrict__ Bhi, const __nv_bfloat16* __restrict__ Blo,
              float* __restrict__ Cc)
{
    extern __shared__ char smem[];
    const uint32_t sbase = smem_u32(smem);
    const int tid = threadIdx.x;
    const int lane = tid & 31;
    const int wid = tid >> 5;
    const int m_blk = blockIdx.y * 128;
    const int n_blk = blockIdx.x * 128;
    const int warp_m = (wid >> 2) * 64;
    const int warp_n = (wid & 3) * 32;

    // ---- async loader (per stage: Ah@0 Al@16K Bh@32K Bl@48K) ----
    // thread handles 4 chunks of 16B per matrix: c = j*256+tid; row=c>>3, q=c&7
    const char* pAh = (const char*)(Ahi + (size_t)m_blk * CC);
    const char* pAl = (const char*)(Alo + (size_t)m_blk * CC);
    const char* pBh = (const char*)(Bhi + (size_t)n_blk * CC);
    const char* pBl = (const char*)(Blo + (size_t)n_blk * CC);

#define LOAD_STAGE(KT, STG) do {                                               \
    const uint32_t sb_ = sbase + (STG) * ST_BYTES;                             \
    const int k0b_ = (KT) * 128;                                               \
    _Pragma("unroll")                                                          \
    for (int j = 0; j < 4; j++) {                                              \
        const int c_ = j * 256 + tid;                                          \
        const int r_ = c_ >> 3, q_ = c_ & 7;                                   \
        const uint32_t so_ = (uint32_t)(r_ * 128 + ((q_ ^ (r_ & 7)) * 16));    \
        const size_t go_ = (size_t)r_ * 2048 + k0b_ + q_ * 16;                 \
        cp16(sb_ + 0     + so_, pAh + go_);                                    \
        cp16(sb_ + 16384 + so_, pAl + go_);                                    \
        cp16(sb_ + 32768 + so_, pBh + go_);                                    \
        cp16(sb_ + 49152 + so_, pBl + go_);                                    \
    }                                                                          \
    CP_COMMIT();                                                               \
} while (0)

    float acc[4][4][4];
#pragma unroll
    for (int a = 0; a < 4; a++)
#pragma unroll
        for (int b = 0; b < 4; b++)
#pragma unroll
            for (int c = 0; c < 4; c++) acc[a][b][c] = 0.0f;

    // ldmatrix per-thread row/chunk mapping
    const int ra = (lane & 7) + (lane & 8);          // A: row within 16-row frag
    const int ka = (lane >> 4) << 3;                 // A: k offset 0/8
    const int rb = (lane & 7) + ((lane & 16) >> 1);  // B: n-row within 16
    const int kb = lane & 8;                         // B: k offset 0/8
    const int sw = lane & 7;                         // swizzle XOR (row&7)

    LOAD_STAGE(0, 0);
    LOAD_STAGE(1, 1);

    for (int kt = 0; kt < 16; kt++) {
        if (kt < 14) CP_WAIT1(); else CP_WAIT0();
        __syncthreads();
        const uint32_t st = sbase + (kt & 1) * ST_BYTES;

#pragma unroll
        for (int k16 = 0; k16 < 64; k16 += 16) {
            uint32_t ah[4][4], al[4][4], bh[2][4], bl[2][4];
#pragma unroll
            for (int mi = 0; mi < 4; mi++) {
                const int m0 = warp_m + mi * 16;
                const uint32_t addr = st + ((uint32_t)(m0 + ra) << 7)
                                    + ((uint32_t)((((k16 + ka) >> 3)) ^ sw) << 4);
                ldm_x4(ah[mi], addr);
                ldm_x4(al[mi], addr + 16384);
            }
#pragma unroll
            for (int bi = 0; bi < 2; bi++) {
                const int n0 = warp_n + bi * 16;
                const uint32_t addr = st + 32768 + ((uint32_t)(n0 + rb) << 7)
                                    + ((uint32_t)(((k16 + kb) >> 3) ^ sw) << 4);
                ldm_x4(bh[bi], addr);
                ldm_x4(bl[bi], addr + 16384);
            }
#pragma unroll
            for (int mi = 0; mi < 4; mi++)
#pragma unroll
                for (int ni = 0; ni < 4; ni++) {
                    uint32_t* bhp = &bh[ni >> 1][(ni & 1) * 2];
                    uint32_t* blp = &bl[ni >> 1][(ni & 1) * 2];
                    mma16816(acc[mi][ni], ah[mi], bhp);
                    mma16816(acc[mi][ni], ah[mi], blp);
                    mma16816(acc[mi][ni], al[mi], bhp);
                }
        }
        __syncthreads();
        if (kt + 2 < 16) LOAD_STAGE(kt + 2, kt & 1);
    }
#undef LOAD_STAGE

    // epilogue: thread holds d0,d1 = C[r][c..c+1], d2,d3 = C[r+8][c..c+1]
    const int er = lane >> 2;
    const int ec = (lane & 3) * 2;
#pragma unroll
    for (int mi = 0; mi < 4; mi++) {
        const int row = m_blk + warp_m + mi * 16 + er;
#pragma unroll
        for (int ni = 0; ni < 4; ni++) {
            const int col = n_blk + warp_n + ni * 8 + ec;
            float v0 = acc[mi][ni][0], v1 = acc[mi][ni][1];
            float v2 = acc[mi][ni][2], v3 = acc[mi][ni][3];
            if (MODE == 1) {
                v0 = 1.0f / (1.0f + expf(-v0));
                v1 = 1.0f / (1.0f + expf(-v1));
                v2 = 1.0f / (1.0f + expf(-v2));
                v3 = 1.0f / (1.0f + expf(-v3));
            }
            float2 lo2 = {v0, v1}, hi2 = {v2, v3};
            *(float2*)&Cc[(size_t)row * CC + col] = lo2;
            *(float2*)&Cc[(size_t)(row + 8) * CC + col] = hi2;
        }
    }
}

// ---------------------------------------------------------------------------
// beta = sigmoid(x @ Wbeta^T + bbeta) : (8192, 16)
// ---------------------------------------------------------------------------
__global__ __launch_bounds__(512)
void beta_kernel(const float* __restrict__ x, const float* __restrict__ Wb,
                 const float* __restrict__ bb, float* __restrict__ Beta)
{
    __shared__ float xs[CC];
    const int row = blockIdx.x;
    const int tid = threadIdx.x;
    for (int i = tid; i < CC; i += 512) xs[i] = x[(size_t)row * CC + i];
    __syncthreads();

    const int h = tid >> 5;
    const int lane = tid & 31;
    const float* wrow = &Wb[(size_t)h * CC];
    float acc = 0.0f;
#pragma unroll 8
    for (int c = lane; c < CC; c += 32) acc = fmaf(xs[c], wrow[c], acc);
#pragma unroll
    for (int off = 16; off > 0; off >>= 1)
        acc += __shfl_xor_sync(0xffffffffu, acc, off);
    if (lane == 0) {
        float v = acc + bb[h];
        Beta[(size_t)row * HH + h] = 1.0f / (1.0f + expf(-v));
    }
}

// ---------------------------------------------------------------------------
// L2-normalize Q and K per (row, head) over D=64
// ---------------------------------------------------------------------------
__global__ __launch_bounds__(256)
void norm_kernel()
{
    const int gw = blockIdx.x * 8 + (threadIdx.x >> 5);
    const int lane = threadIdx.x & 31;
    const int which = gw & 1;
    const int rem = gw >> 1;
    const int row = rem >> 4;
    const int h = rem & 15;
    float* P = which ? g_K : g_Q;
    float* p = &P[(size_t)row * CC + h * DD];
    float v0 = p[lane];
    float v1 = p[lane + 32];
    float s = v0 * v0 + v1 * v1;
#pragma unroll
    for (int off = 16; off > 0; off >>= 1)
        s += __shfl_xor_sync(0xffffffffu, s, off);
    float n = sqrtf(s);
    float scale = 1.0f / fmaxf(n, 1e-12f);
    p[lane]      = v0 * scale;
    p[lane + 32] = v1 * scale;
}

// ---------------------------------------------------------------------------
// Delta-rule scan. One block per (b,h). 256 threads.
// Prefetch depth 4 (static unroll x4), float4 smem reads, 1 barrier/step.
// ---------------------------------------------------------------------------
__global__ __launch_bounds__(256, 1)
void scan_kernel()
{
    const int b = blockIdx.x >> 4;
    const int h = blockIdx.x & 15;
    __shared__ float s[2][256];      // [0:64)q [64:128)k [128:192)v [192:256)g
    __shared__ float sbv[2];

    const int t = threadIdx.x;
    const int d = t >> 2;
    const int cg = t & 3;

    const int arr = t >> 6;
    const int idx = t & 63;
    const float* src = (arr == 0) ? g_Q : (arr == 1) ? g_K : (arr == 2) ? g_V : g_G;
    const size_t rbase = (size_t)b * TT;
    const size_t coff = (size_t)h * DD + idx;

    float Mreg[16];
#pragma unroll
    for (int j = 0; j < 16; j++) Mreg[j] = 0.0f;

    float pf0 = src[(rbase + 0) * CC + coff];
    float pf1 = src[(rbase + 1) * CC + coff];
    float pf2 = src[(rbase + 2) * CC + coff];
    float pf3 = src[(rbase + 3) * CC + coff];
    float pb0 = 0, pb1 = 0, pb2 = 0, pb3 = 0;
    if (t == 0) {
        pb0 = g_Beta[(rbase + 0) * HH + h];
        pb1 = g_Beta[(rbase + 1) * HH + h];
        pb2 = g_Beta[(rbase + 2) * HH + h];
        pb3 = g_Beta[(rbase + 3) * HH + h];
    }
    s[0][t] = pf0;
    if (t == 0) sbv[0] = pb0;
    __syncthreads();

#define SCAN_STEP(STEP, BUF, PF_NEXT, PB_NEXT, PF_SELF, PB_SELF)                      \
    {                                                                                 \
        const int ls = ((STEP) + 4 < TT) ? (STEP) + 4 : TT - 1;                       \
        float nv = src[(rbase + ls) * CC + coff];                                     \
        float nb = 0.0f;                                                              \
        if (t == 0) nb = g_Beta[(rbase + ls) * HH + h];                               \
        s[(BUF) ^ 1][t] = PF_NEXT;                                                    \
        if (t == 0) sbv[(BUF) ^ 1] = PB_NEXT;                                         \
        const float4* sq4 = (const float4*)&s[BUF][0];                                \
        const float4* sk4 = (const float4*)&s[BUF][64];                               \
        const float sb = sbv[BUF];                                                    \
        float po = 0.0f, pk = 0.0f;                                                   \
        float kreg[16];                                                               \
        _Pragma("unroll")                                                             \
        for (int jj = 0; jj < 4; jj++) {                                              \
            float4 qv = sq4[cg * 4 + jj];                                             \
            float4 kv = sk4[cg * 4 + jj];                                             \
            kreg[jj*4+0] = kv.x; kreg[jj*4+1] = kv.y;                                 \
            kreg[jj*4+2] = kv.z; kreg[jj*4+3] = kv.w;                                 \
            po = fmaf(Mreg[jj*4+0], qv.x, po); pk = fmaf(Mreg[jj*4+0], kv.x, pk);     \
            po = fmaf(Mreg[jj*4+1], qv.y, po); pk = fmaf(Mreg[jj*4+1], kv.y, pk);     \
            po = fmaf(Mreg[jj*4+2], qv.z, po); pk = fmaf(Mreg[jj*4+2], kv.z, pk);     \
            po = fmaf(Mreg[jj*4+3], qv.w, po); pk = fmaf(Mreg[jj*4+3], kv.w, pk);     \
        }                                                                             \
        po += __shfl_xor_sync(0xffffffffu, po, 1);                                    \
        pk += __shfl_xor_sync(0xffffffffu, pk, 1);                                    \
        po += __shfl_xor_sync(0xffffffffu, po, 2);                                    \
        pk += __shfl_xor_sync(0xffffffffu, pk, 2);                                    \
        const float dv = s[BUF][128 + d] - pk;                                        \
        const float bdv = sb * dv;                                                    \
        _Pragma("unroll")                                                             \
        for (int jj = 0; jj < 16; jj++)                                               \
            Mreg[jj] = fmaf(bdv, kreg[jj], Mreg[jj]);                                 \
        if (cg == 0)                                                                  \
            g_OG[(rbase + (STEP)) * CC + h * DD + d] = s[BUF][192 + d] * po;          \
        PF_SELF = nv; PB_SELF = nb;                                                   \
        __syncthreads();                                                              \
    }

    for (int st = 0; st < TT; st += 4) {
        SCAN_STEP(st + 0, 0, pf1, pb1, pf0, pb0);
        SCAN_STEP(st + 1, 1, pf2, pb2, pf1, pb1);
        SCAN_STEP(st + 2, 0, pf3, pb3, pf2, pb2);
        SCAN_STEP(st + 3, 1, pf0, pb0, pf3, pb3);
    }
#undef SCAN_STEP
}

// ---------------------------------------------------------------------------
extern "C" void kernel_launch(void* const* d_in, const int* in_sizes, int n_in,
                              void* d_out, int out_size)
{
    const float* x     = (const float*)d_in[0];
    const float* Wq    = (const float*)d_in[1];
    const float* Wk    = (const float*)d_in[2];
    const float* Wv    = (const float*)d_in[3];
    const float* Wbeta = (const float*)d_in[4];
    const float* bbeta = (const float*)d_in[5];
    const float* Wgate = (const float*)d_in[6];
    const float* Wo    = (const float*)d_in[7];
    float* out = (float*)d_out;

    float *Qp, *Kp, *Vp, *Gp, *OGp, *Bp;
    cudaGetSymbolAddress((void**)&Qp,  g_Q);
    cudaGetSymbolAddress((void**)&Kp,  g_K);
    cudaGetSymbolAddress((void**)&Vp,  g_V);
    cudaGetSymbolAddress((void**)&Gp,  g_G);
    cudaGetSymbolAddress((void**)&OGp, g_OG);
    cudaGetSymbolAddress((void**)&Bp,  g_Beta);
    __nv_bfloat16 *xhi, *xlo, *whi, *wlo, *oghi, *oglo;
    cudaGetSymbolAddress((void**)&xhi,  g_xhi);
    cudaGetSymbolAddress((void**)&xlo,  g_xlo);
    cudaGetSymbolAddress((void**)&whi,  g_whi);
    cudaGetSymbolAddress((void**)&wlo,  g_wlo);
    cudaGetSymbolAddress((void**)&oghi, g_oghi);
    cudaGetSymbolAddress((void**)&oglo, g_oglo);

    cudaFuncSetAttribute(mma_gemm<0>, cudaFuncAttributeMaxDynamicSharedMemorySize, GEMM_SMEM);
    cudaFuncSetAttribute(mma_gemm<1>, cudaFuncAttributeMaxDynamicSharedMemorySize, GEMM_SMEM);

    const int WSZ = CC * CC;

    // split conversions
    conv_hl_kernel<<<MROWS * CC / 4 / 256, 256>>>(x, xhi, xlo);
    conv_hl_kernel<<<WSZ / 4 / 256, 256>>>(Wq,    whi + 0 * WSZ, wlo + 0 * WSZ);
    conv_hl_kernel<<<WSZ / 4 / 256, 256>>>(Wk,    whi + 1 * WSZ, wlo + 1 * WSZ);
    conv_hl_kernel<<<WSZ / 4 / 256, 256>>>(Wv,    whi + 2 * WSZ, wlo + 2 * WSZ);
    conv_hl_kernel<<<WSZ / 4 / 256, 256>>>(Wgate, whi + 3 * WSZ, wlo + 3 * WSZ);
    conv_hl_kernel<<<WSZ / 4 / 256, 256>>>(Wo,    whi + 4 * WSZ, wlo + 4 * WSZ);

    dim3 ggrid(CC / 128, MROWS / 128);
    mma_gemm<0><<<ggrid, 256, GEMM_SMEM>>>(xhi, xlo, whi + 0 * WSZ, wlo + 0 * WSZ, Qp);
    mma_gemm<0><<<ggrid, 256, GEMM_SMEM>>>(xhi, xlo, whi + 1 * WSZ, wlo + 1 * WSZ, Kp);
    mma_gemm<0><<<ggrid, 256, GEMM_SMEM>>>(xhi, xlo, whi + 2 * WSZ, wlo + 2 * WSZ, Vp);
    mma_gemm<1><<<ggrid, 256, GEMM_SMEM>>>(xhi, xlo, whi + 3 * WSZ, wlo + 3 * WSZ, Gp);

    beta_kernel<<<MROWS, 512>>>(x, Wbeta, bbeta, Bp);
    norm_kernel<<<(2 * MROWS * HH) / 8, 256>>>();
    scan_kernel<<<BB * HH, 256>>>();

    conv_hl_kernel<<<MROWS * CC / 4 / 256, 256>>>(OGp, oghi, oglo);
    mma_gemm<0><<<ggrid, 256, GEMM_SMEM>>>(oghi, oglo, whi + 4 * WSZ, wlo + 4 * WSZ, out);
}

// round 6
// speedup vs baseline: 2.9591x; 1.0530x over previous
#include <cuda_runtime.h>
#include <cuda_bf16.h>
#include <math.h>
#include <stdint.h>

// Problem dims (fixed)
#define BB 4
#define TT 2048
#define CC 1024
#define HH 16
#define DD 64
#define MROWS (BB*TT)          // 8192
#define NFUSE 4096             // Q|K|V|G fused width

// ---------------------------------------------------------------------------
// Device scratch (cudaMalloc banned)
// ---------------------------------------------------------------------------
__device__ float g_QKVG[MROWS*NFUSE];     // fused Q|K|V|G, row stride 4096
__device__ float g_OG[MROWS*CC];
__device__ float g_Beta[MROWS*HH];

__device__ __nv_bfloat16 g_xhi[MROWS*CC];
__device__ __nv_bfloat16 g_xlo[MROWS*CC];
__device__ __nv_bfloat16 g_whi[5*CC*CC];
__device__ __nv_bfloat16 g_wlo[5*CC*CC];
__device__ __nv_bfloat16 g_oghi[MROWS*CC];
__device__ __nv_bfloat16 g_oglo[MROWS*CC];

// ---------------------------------------------------------------------------
// PTX helpers (base-ISA only: mma.sync / ldmatrix / cp.async)
// ---------------------------------------------------------------------------
__device__ __forceinline__ uint32_t smem_u32(const void* p) {
    uint32_t a;
    asm("{ .reg .u64 t; cvta.to.shared.u64 t, %1; cvt.u32.u64 %0, t; }" : "=r"(a) : "l"(p));
    return a;
}
__device__ __forceinline__ void cp16(uint32_t dst, const void* src) {
    asm volatile("cp.async.cg.shared.global [%0], [%1], 16;" :: "r"(dst), "l"(src));
}
#define CP_COMMIT() asm volatile("cp.async.commit_group;" ::: "memory")
#define CP_WAIT1()  asm volatile("cp.async.wait_group 1;" ::: "memory")
#define CP_WAIT0()  asm volatile("cp.async.wait_group 0;" ::: "memory")

__device__ __forceinline__ void ldm_x4(uint32_t* r, uint32_t addr) {
    asm volatile("ldmatrix.sync.aligned.m8n8.x4.shared.b16 {%0,%1,%2,%3}, [%4];"
        : "=r"(r[0]), "=r"(r[1]), "=r"(r[2]), "=r"(r[3]) : "r"(addr));
}
__device__ __forceinline__ void mma16816(float* d, const uint32_t* a, const uint32_t* b) {
    asm volatile("mma.sync.aligned.m16n8k16.row.col.f32.bf16.bf16.f32 "
        "{%0,%1,%2,%3}, {%4,%5,%6,%7}, {%8,%9}, {%0,%1,%2,%3};"
        : "+f"(d[0]), "+f"(d[1]), "+f"(d[2]), "+f"(d[3])
        : "r"(a[0]), "r"(a[1]), "r"(a[2]), "r"(a[3]), "r"(b[0]), "r"(b[1]));
}

// ---------------------------------------------------------------------------
// fp32 -> (bf16 hi, bf16 lo) split conversion, float4-vectorized
// ---------------------------------------------------------------------------
__global__ __launch_bounds__(256)
void conv_hl_kernel(const float* __restrict__ in, __nv_bfloat16* __restrict__ hi,
                    __nv_bfloat16* __restrict__ lo)
{
    const int i = blockIdx.x * 256 + threadIdx.x;   // float4 index
    float4 v = ((const float4*)in)[i];
    __nv_bfloat16 h0 = __float2bfloat16(v.x);
    __nv_bfloat16 h1 = __float2bfloat16(v.y);
    __nv_bfloat16 h2 = __float2bfloat16(v.z);
    __nv_bfloat16 h3 = __float2bfloat16(v.w);
    __nv_bfloat16 l0 = __float2bfloat16(v.x - __bfloat162float(h0));
    __nv_bfloat16 l1 = __float2bfloat16(v.y - __bfloat162float(h1));
    __nv_bfloat16 l2 = __float2bfloat16(v.z - __bfloat162float(h2));
    __nv_bfloat16 l3 = __float2bfloat16(v.w - __bfloat162float(h3));
    ushort4 hv = { __bfloat16_as_ushort(h0), __bfloat16_as_ushort(h1),
                   __bfloat16_as_ushort(h2), __bfloat16_as_ushort(h3) };
    ushort4 lv = { __bfloat16_as_ushort(l0), __bfloat16_as_ushort(l1),
                   __bfloat16_as_ushort(l2), __bfloat16_as_ushort(l3) };
    ((ushort4*)hi)[i] = hv;
    ((ushort4*)lo)[i] = lv;
}

// ---------------------------------------------------------------------------
// HMMA split-bf16 GEMM: C[8192,N] = A[8192,1024] @ B[N,1024]^T
//   C = Ahi*Bhi + Ahi*Blo + Alo*Bhi  (fp32 accum)
// CTA tile 128x128, BK=32, 3-stage cp.async, 96KB smem -> 2 CTAs/SM.
// 8 warps (2x4), warp tile 64x32. Sigmoid applied for cols >= sig_start.
// SMEM stage layout (32KB): Ah@0  Al@8K  Bh@16K  Bl@24K, rows of 64B,
// 16B-chunk swizzle: phys_q = q ^ ((row>>1)&3)  (conflict-free ldmatrix).
// ---------------------------------------------------------------------------
#define STG_B 32768
#define NSTG  3
#define GEMM_SMEM (NSTG*STG_B)   // 96 KB

__global__ __launch_bounds__(256, 2)
void mma_gemm(const __nv_bfloat16* __restrict__ Ahi, const __nv_bfloat16* __restrict__ Alo,
              const __nv_bfloat16* __restrict__ Bhi, const __nv_bfloat16* __restrict__ Blo,
              float* __restrict__ Cc, int ldc, int sig_start)
{
    extern __shared__ char smem[];
    const uint32_t sbase = smem_u32(smem);
    const int tid = threadIdx.x;
    const int lane = tid & 31;
    const int wid = tid >> 5;
    const int m_blk = blockIdx.y * 128;
    const int n_blk = blockIdx.x * 128;
    const int warp_m = (wid >> 2) * 64;
    const int warp_n = (wid & 3) * 32;

    const char* pAh = (const char*)(Ahi + (size_t)m_blk * CC);
    const char* pAl = (const char*)(Alo + (size_t)m_blk * CC);
    const char* pBh = (const char*)(Bhi + (size_t)n_blk * CC);
    const char* pBl = (const char*)(Blo + (size_t)n_blk * CC);

    // loader: per stage per matrix 8KB = 512 x 16B chunks; 2 per thread
#define LOAD_STAGE(KT, STG) do {                                               \
    const uint32_t sb_ = sbase + (STG) * STG_B;                                \
    const int k0b_ = (KT) * 64;                                                \
    _Pragma("unroll")                                                          \
    for (int j = 0; j < 2; j++) {                                              \
        const int c_ = j * 256 + tid;                                          \
        const int r_ = c_ >> 2, q_ = c_ & 3;                                   \
        const uint32_t so_ = (uint32_t)(r_ * 64 + ((q_ ^ ((r_ >> 1) & 3)) * 16)); \
        const size_t go_ = (size_t)r_ * 2048 + k0b_ + q_ * 16;                 \
        cp16(sb_ + 0     + so_, pAh + go_);                                    \
        cp16(sb_ + 8192  + so_, pAl + go_);                                    \
        cp16(sb_ + 16384 + so_, pBh + go_);                                    \
        cp16(sb_ + 24576 + so_, pBl + go_);                                    \
    }                                                                          \
    CP_COMMIT();                                                               \
} while (0)

    float acc[4][4][4];
#pragma unroll
    for (int a = 0; a < 4; a++)
#pragma unroll
        for (int b = 0; b < 4; b++)
#pragma unroll
            for (int c = 0; c < 4; c++) acc[a][b][c] = 0.0f;

    // ldmatrix per-thread mapping
    const int ra = lane & 15;                        // A row within 16-row frag
    const int qa_add = lane >> 4;                    // A k-chunk add (0/1)
    const int rb = (lane & 7) + ((lane & 16) >> 1);  // B row within 16
    const int qb_add = (lane & 8) >> 3;              // B k-chunk add (0/1)

    LOAD_STAGE(0, 0);
    LOAD_STAGE(1, 1);

    for (int kt = 0; kt < 32; kt++) {
        if (kt + 1 < 32) CP_WAIT1(); else CP_WAIT0();
        __syncthreads();
        const uint32_t st = sbase + (kt % NSTG) * STG_B;

#pragma unroll
        for (int k16 = 0; k16 < 2; k16++) {
            uint32_t bh[2][4], bl[2][4];
#pragma unroll
            for (int bi = 0; bi < 2; bi++) {
                const int n0 = warp_n + bi * 16;
                const int row = n0 + rb;
                const uint32_t q = (uint32_t)(((k16 << 1) + qb_add) ^ ((row >> 1) & 3));
                const uint32_t addr = st + 16384 + (uint32_t)row * 64 + q * 16;
                ldm_x4(bh[bi], addr);
                ldm_x4(bl[bi], addr + 8192);
            }
#pragma unroll
            for (int mi = 0; mi < 4; mi++) {
                const int m0 = warp_m + mi * 16;
                const int row = m0 + ra;
                const uint32_t q = (uint32_t)(((k16 << 1) + qa_add) ^ ((row >> 1) & 3));
                const uint32_t addr = st + (uint32_t)row * 64 + q * 16;
                uint32_t ah[4], al[4];
                ldm_x4(ah, addr);
                ldm_x4(al, addr + 8192);
#pragma unroll
                for (int ni = 0; ni < 4; ni++) {
                    uint32_t* bhp = &bh[ni >> 1][(ni & 1) * 2];
                    uint32_t* blp = &bl[ni >> 1][(ni & 1) * 2];
                    mma16816(acc[mi][ni], ah, bhp);
                    mma16816(acc[mi][ni], ah, blp);
                    mma16816(acc[mi][ni], al, bhp);
                }
            }
        }
        __syncthreads();
        if (kt + 2 < 32) LOAD_STAGE(kt + 2, (kt + 2) % NSTG);
    }
#undef LOAD_STAGE

    // epilogue
    const int er = lane >> 2;
    const int ec = (lane & 3) * 2;
#pragma unroll
    for (int mi = 0; mi < 4; mi++) {
        const int row = m_blk + warp_m + mi * 16 + er;
#pragma unroll
        for (int ni = 0; ni < 4; ni++) {
            const int col = n_blk + warp_n + ni * 8 + ec;
            float v0 = acc[mi][ni][0], v1 = acc[mi][ni][1];
            float v2 = acc[mi][ni][2], v3 = acc[mi][ni][3];
            if (col >= sig_start) {
                v0 = 1.0f / (1.0f + expf(-v0));
                v1 = 1.0f / (1.0f + expf(-v1));
                v2 = 1.0f / (1.0f + expf(-v2));
                v3 = 1.0f / (1.0f + expf(-v3));
            }
            float2 lo2 = {v0, v1}, hi2 = {v2, v3};
            *(float2*)&Cc[(size_t)row * ldc + col] = lo2;
            *(float2*)&Cc[(size_t)(row + 8) * ldc + col] = hi2;
        }
    }
}

// ---------------------------------------------------------------------------
// beta = sigmoid(x @ Wbeta^T + bbeta) : (8192, 16)
// ---------------------------------------------------------------------------
__global__ __launch_bounds__(512)
void beta_kernel(const float* __restrict__ x, const float* __restrict__ Wb,
                 const float* __restrict__ bb, float* __restrict__ Beta)
{
    __shared__ float xs[CC];
    const int row = blockIdx.x;
    const int tid = threadIdx.x;
    for (int i = tid; i < CC; i += 512) xs[i] = x[(size_t)row * CC + i];
    __syncthreads();

    const int h = tid >> 5;
    const int lane = tid & 31;
    const float* wrow = &Wb[(size_t)h * CC];
    float acc = 0.0f;
#pragma unroll 8
    for (int c = lane; c < CC; c += 32) acc = fmaf(xs[c], wrow[c], acc);
#pragma unroll
    for (int off = 16; off > 0; off >>= 1)
        acc += __shfl_xor_sync(0xffffffffu, acc, off);
    if (lane == 0) {
        float v = acc + bb[h];
        Beta[(size_t)row * HH + h] = 1.0f / (1.0f + expf(-v));
    }
}

// ---------------------------------------------------------------------------
// L2-normalize Q and K per (row, head) over D=64 (in fused QKVG buffer)
// ---------------------------------------------------------------------------
__global__ __launch_bounds__(256)
void norm_kernel()
{
    const int gw = blockIdx.x * 8 + (threadIdx.x >> 5);
    const int lane = threadIdx.x & 31;
    const int which = gw & 1;                 // 0=Q quarter, 1=K quarter
    const int rem = gw >> 1;
    const int row = rem >> 4;
    const int h = rem & 15;
    float* p = &g_QKVG[(size_t)row * NFUSE + which * CC + h * DD];
    float v0 = p[lane];
    float v1 = p[lane + 32];
    float s = v0 * v0 + v1 * v1;
#pragma unroll
    for (int off = 16; off > 0; off >>= 1)
        s += __shfl_xor_sync(0xffffffffu, s, off);
    float n = sqrtf(s);
    float scale = 1.0f / fmaxf(n, 1e-12f);
    p[lane]      = v0 * scale;
    p[lane + 32] = v1 * scale;
}

// ---------------------------------------------------------------------------
// Delta-rule scan. One block per (b,h). 256 threads.
// Prefetch depth 4, float4 smem reads, dual accumulators, 1 barrier/step.
// Reads fused QKVG (quarters q/k/v/g), writes g_OG = gate*o.
// ---------------------------------------------------------------------------
__global__ __launch_bounds__(256, 1)
void scan_kernel()
{
    const int b = blockIdx.x >> 4;
    const int h = blockIdx.x & 15;
    __shared__ float s[2][256];      // [0:64)q [64:128)k [128:192)v [192:256)g
    __shared__ float sbv[2];

    const int t = threadIdx.x;
    const int d = t >> 2;
    const int cg = t & 3;

    const int arr = t >> 6;          // quarter: 0=q 1=k 2=v 3=g
    const int idx = t & 63;
    const float* src = g_QKVG + (size_t)arr * CC + (size_t)h * DD + idx;
    const size_t rbase = (size_t)b * TT;

    float Mreg[16];
#pragma unroll
    for (int j = 0; j < 16; j++) Mreg[j] = 0.0f;

    float pf0 = src[(rbase + 0) * NFUSE];
    float pf1 = src[(rbase + 1) * NFUSE];
    float pf2 = src[(rbase + 2) * NFUSE];
    float pf3 = src[(rbase + 3) * NFUSE];
    float pb0 = 0, pb1 = 0, pb2 = 0, pb3 = 0;
    if (t == 0) {
        pb0 = g_Beta[(rbase + 0) * HH + h];
        pb1 = g_Beta[(rbase + 1) * HH + h];
        pb2 = g_Beta[(rbase + 2) * HH + h];
        pb3 = g_Beta[(rbase + 3) * HH + h];
    }
    s[0][t] = pf0;
    if (t == 0) sbv[0] = pb0;
    __syncthreads();

#define SCAN_STEP(STEP, BUF, PF_NEXT, PB_NEXT, PF_SELF, PB_SELF)                      \
    {                                                                                 \
        const int ls = ((STEP) + 4 < TT) ? (STEP) + 4 : TT - 1;                       \
        float nv = src[(rbase + ls) * NFUSE];                                         \
        float nb = 0.0f;                                                              \
        if (t == 0) nb = g_Beta[(rbase + ls) * HH + h];                               \
        s[(BUF) ^ 1][t] = PF_NEXT;                                                    \
        if (t == 0) sbv[(BUF) ^ 1] = PB_NEXT;                                         \
        const float4* sq4 = (const float4*)&s[BUF][0];                                \
        const float4* sk4 = (const float4*)&s[BUF][64];                               \
        const float sb = sbv[BUF];                                                    \
        float poA = 0.0f, pkA = 0.0f, poB = 0.0f, pkB = 0.0f;                         \
        float kreg[16];                                                               \
        _Pragma("unroll")                                                             \
        for (int jj = 0; jj < 2; jj++) {                                              \
            float4 qv = sq4[cg * 4 + jj];                                             \
            float4 kv = sk4[cg * 4 + jj];                                             \
            kreg[jj*4+0] = kv.x; kreg[jj*4+1] = kv.y;                                 \
            kreg[jj*4+2] = kv.z; kreg[jj*4+3] = kv.w;                                 \
            poA = fmaf(Mreg[jj*4+0], qv.x, poA); pkA = fmaf(Mreg[jj*4+0], kv.x, pkA); \
            poA = fmaf(Mreg[jj*4+1], qv.y, poA); pkA = fmaf(Mreg[jj*4+1], kv.y, pkA); \
            poA = fmaf(Mreg[jj*4+2], qv.z, poA); pkA = fmaf(Mreg[jj*4+2], kv.z, pkA); \
            poA = fmaf(Mreg[jj*4+3], qv.w, poA); pkA = fmaf(Mreg[jj*4+3], kv.w, pkA); \
        }                                                                             \
        _Pragma("unroll")                                                             \
        for (int jj = 2; jj < 4; jj++) {                                              \
            float4 qv = sq4[cg * 4 + jj];                                             \
            float4 kv = sk4[cg * 4 + jj];                                             \
            kreg[jj*4+0] = kv.x; kreg[jj*4+1] = kv.y;                                 \
            kreg[jj*4+2] = kv.z; kreg[jj*4+3] = kv.w;                                 \
            poB = fmaf(Mreg[jj*4+0], qv.x, poB); pkB = fmaf(Mreg[jj*4+0], kv.x, pkB); \
            poB = fmaf(Mreg[jj*4+1], qv.y, poB); pkB = fmaf(Mreg[jj*4+1], kv.y, pkB); \
            poB = fmaf(Mreg[jj*4+2], qv.z, poB); pkB = fmaf(Mreg[jj*4+2], kv.z, pkB); \
            poB = fmaf(Mreg[jj*4+3], qv.w, poB); pkB = fmaf(Mreg[jj*4+3], kv.w, pkB); \
        }                                                                             \
        float po = poA + poB, pk = pkA + pkB;                                         \
        po += __shfl_xor_sync(0xffffffffu, po, 1);                                    \
        pk += __shfl_xor_sync(0xffffffffu, pk, 1);                                    \
        po += __shfl_xor_sync(0xffffffffu, po, 2);                                    \
        pk += __shfl_xor_sync(0xffffffffu, pk, 2);                                    \
        const float dv = s[BUF][128 + d] - pk;                                        \
        const float bdv = sb * dv;                                                    \
        _Pragma("unroll")                                                             \
        for (int jj = 0; jj < 16; jj++)                                               \
            Mreg[jj] = fmaf(bdv, kreg[jj], Mreg[jj]);                                 \
        if (cg == 0)                                                                  \
            g_OG[(rbase + (STEP)) * CC + h * DD + d] = s[BUF][192 + d] * po;          \
        PF_SELF = nv; PB_SELF = nb;                                                   \
        __syncthreads();                                                              \
    }

    for (int st = 0; st < TT; st += 4) {
        SCAN_STEP(st + 0, 0, pf1, pb1, pf0, pb0);
        SCAN_STEP(st + 1, 1, pf2, pb2, pf1, pb1);
        SCAN_STEP(st + 2, 0, pf3, pb3, pf2, pb2);
        SCAN_STEP(st + 3, 1, pf0, pb0, pf3, pb3);
    }
#undef SCAN_STEP
}

// ---------------------------------------------------------------------------
extern "C" void kernel_launch(void* const* d_in, const int* in_sizes, int n_in,
                              void* d_out, int out_size)
{
    const float* x     = (const float*)d_in[0];
    const float* Wq    = (const float*)d_in[1];
    const float* Wk    = (const float*)d_in[2];
    const float* Wv    = (const float*)d_in[3];
    const float* Wbeta = (const float*)d_in[4];
    const float* bbeta = (const float*)d_in[5];
    const float* Wgate = (const float*)d_in[6];
    const float* Wo    = (const float*)d_in[7];
    float* out = (float*)d_out;

    float *QKVGp, *OGp, *Bp;
    cudaGetSymbolAddress((void**)&QKVGp, g_QKVG);
    cudaGetSymbolAddress((void**)&OGp,   g_OG);
    cudaGetSymbolAddress((void**)&Bp,    g_Beta);
    __nv_bfloat16 *xhi, *xlo, *whi, *wlo, *oghi, *oglo;
    cudaGetSymbolAddress((void**)&xhi,  g_xhi);
    cudaGetSymbolAddress((void**)&xlo,  g_xlo);
    cudaGetSymbolAddress((void**)&whi,  g_whi);
    cudaGetSymbolAddress((void**)&wlo,  g_wlo);
    cudaGetSymbolAddress((void**)&oghi, g_oghi);
    cudaGetSymbolAddress((void**)&oglo, g_oglo);

    cudaFuncSetAttribute(mma_gemm, cudaFuncAttributeMaxDynamicSharedMemorySize, GEMM_SMEM);

    const int WSZ = CC * CC;

    // split conversions
    conv_hl_kernel<<<MROWS * CC / 4 / 256, 256>>>(x, xhi, xlo);
    conv_hl_kernel<<<WSZ / 4 / 256, 256>>>(Wq,    whi + 0 * WSZ, wlo + 0 * WSZ);
    conv_hl_kernel<<<WSZ / 4 / 256, 256>>>(Wk,    whi + 1 * WSZ, wlo + 1 * WSZ);
    conv_hl_kernel<<<WSZ / 4 / 256, 256>>>(Wv,    whi + 2 * WSZ, wlo + 2 * WSZ);
    conv_hl_kernel<<<WSZ / 4 / 256, 256>>>(Wgate, whi + 3 * WSZ, wlo + 3 * WSZ);
    conv_hl_kernel<<<WSZ / 4 / 256, 256>>>(Wo,    whi + 4 * WSZ, wlo + 4 * WSZ);

    // fused QKVG projection: N=4096, sigmoid on gate quarter (cols >= 3072)
    dim3 fgrid(NFUSE / 128, MROWS / 128);
    mma_gemm<<<fgrid, 256, GEMM_SMEM>>>(xhi, xlo, whi, wlo, QKVGp, NFUSE, 3 * CC);

    beta_kernel<<<MROWS, 512>>>(x, Wbeta, bbeta, Bp);
    norm_kernel<<<(2 * MROWS * HH) / 8, 256>>>();
    scan_kernel<<<BB * HH, 256>>>();

    conv_hl_kernel<<<MROWS * CC / 4 / 256, 256>>>(OGp, oghi, oglo);
    dim3 ogrid(CC / 128, MROWS / 128);
    mma_gemm<<<ogrid, 256, GEMM_SMEM>>>(oghi, oglo, whi + 4 * WSZ, wlo + 4 * WSZ,
                                        out, CC, 1 << 30);
}

// round 8
// speedup vs baseline: 3.3394x; 1.1285x over previous
#include <cuda_runtime.h>
#include <cuda_bf16.h>
#include <math.h>
#include <stdint.h>

// Problem dims (fixed)
#define BB 4
#define TT 2048
#define CC 1024
#define HH 16
#define DD 64
#define MROWS (BB*TT)          // 8192
#define NFUSE 4096             // Q|K|V|G fused width

// ---------------------------------------------------------------------------
// Device scratch (cudaMalloc banned)
// ---------------------------------------------------------------------------
__device__ float g_QKVG[MROWS*NFUSE];     // fused Q|K|V|G, row stride 4096
__device__ float g_OG[MROWS*CC];          // tf32-rounded gate*o
__device__ float g_Beta[MROWS*HH];
__device__ float g_xt[MROWS*CC];          // tf32-rounded x
__device__ float g_wt[5*CC*CC];           // tf32-rounded Wq|Wk|Wv|Wgate|Wo

// ---------------------------------------------------------------------------
// PTX helpers (base-ISA only: mma.sync / ldmatrix / cp.async / cvt.tf32)
// ---------------------------------------------------------------------------
__device__ __forceinline__ uint32_t smem_u32(const void* p) {
    uint32_t a;
    asm("{ .reg .u64 t; cvta.to.shared.u64 t, %1; cvt.u32.u64 %0, t; }" : "=r"(a) : "l"(p));
    return a;
}
__device__ __forceinline__ void cp16(uint32_t dst, const void* src) {
    asm volatile("cp.async.cg.shared.global [%0], [%1], 16;" :: "r"(dst), "l"(src));
}
#define CP_COMMIT() asm volatile("cp.async.commit_group;" ::: "memory")
#define CP_WAIT1()  asm volatile("cp.async.wait_group 1;" ::: "memory")
#define CP_WAIT0()  asm volatile("cp.async.wait_group 0;" ::: "memory")

__device__ __forceinline__ void ldm_x4(uint32_t* r, uint32_t addr) {
    asm volatile("ldmatrix.sync.aligned.m8n8.x4.shared.b16 {%0,%1,%2,%3}, [%4];"
        : "=r"(r[0]), "=r"(r[1]), "=r"(r[2]), "=r"(r[3]) : "r"(addr));
}
// tf32 mma: D += A*B, A: 4 regs (a0..a3), B: 2 regs
__device__ __forceinline__ void mma1688(float* d, uint32_t a0, uint32_t a1,
                                        uint32_t a2, uint32_t a3,
                                        uint32_t b0, uint32_t b1) {
    asm volatile("mma.sync.aligned.m16n8k8.row.col.f32.tf32.tf32.f32 "
        "{%0,%1,%2,%3}, {%4,%5,%6,%7}, {%8,%9}, {%0,%1,%2,%3};"
        : "+f"(d[0]), "+f"(d[1]), "+f"(d[2]), "+f"(d[3])
        : "r"(a0), "r"(a1), "r"(a2), "r"(a3), "r"(b0), "r"(b1));
}
__device__ __forceinline__ float tf32r(float x) {
    float r;
    asm("cvt.rna.tf32.f32 %0, %1;" : "=f"(r) : "f"(x));
    return r;
}

// ---------------------------------------------------------------------------
// fp32 -> tf32-rounded fp32 (unbiased round-to-nearest), float4-vectorized
// ---------------------------------------------------------------------------
__global__ __launch_bounds__(256)
void tf32_round_kernel(const float* __restrict__ in, float* __restrict__ out)
{
    const int i = blockIdx.x * 256 + threadIdx.x;
    float4 v = ((const float4*)in)[i];
    v.x = tf32r(v.x); v.y = tf32r(v.y); v.z = tf32r(v.z); v.w = tf32r(v.w);
    ((float4*)out)[i] = v;
}

// ---------------------------------------------------------------------------
// TF32 HMMA GEMM: C[8192,N] = A[8192,1024] @ B[N,1024]^T  (fp32 in/out)
// CTA tile 128x128, BK=32, 3-stage cp.async, 96KB smem -> 2 CTAs/SM.
// 8 warps (2x4), warp tile 64x32. Sigmoid applied for cols >= sig_start.
// SMEM stage (32KB): A[128][32]f32 @0, B[128][32]f32 @16K; rows = 128B,
// 16B-chunk swizzle phys_q = q ^ (row&7) (conflict-free ldmatrix).
// tf32 fragments via ldmatrix.x4 over fp32 rows treated as b16 tiles:
//   tile = 8 rows x 4 fp32 -> lane l gets (row l>>2, col l&3) = tf32 frag slot.
// A x4 tiles -> regs {a0,a1,a2,a3} in IDENTITY order (verified against the
// working bf16 layout; R7's permutation was the correctness bug).
// ---------------------------------------------------------------------------
#define STG_B 32768
#define NSTG  3
#define GEMM_SMEM (NSTG*STG_B)   // 96 KB

__global__ __launch_bounds__(256, 2)
void mma_gemm(const float* __restrict__ Ag, const float* __restrict__ Bg,
              float* __restrict__ Cc, int ldc, int sig_start)
{
    extern __shared__ char smem[];
    const uint32_t sbase = smem_u32(smem);
    const int tid = threadIdx.x;
    const int lane = tid & 31;
    const int wid = tid >> 5;
    const int m_blk = blockIdx.y * 128;
    const int n_blk = blockIdx.x * 128;
    const int warp_m = (wid >> 2) * 64;
    const int warp_n = (wid & 3) * 32;

    const char* pA = (const char*)(Ag + (size_t)m_blk * CC);
    const char* pB = (const char*)(Bg + (size_t)n_blk * CC);

    // loader: per stage per matrix 16KB = 1024 x 16B chunks; 4 per thread
#define LOAD_STAGE(KT, STG) do {                                               \
    const uint32_t sb_ = sbase + (STG) * STG_B;                                \
    const int k0b_ = (KT) * 128;   /* 32 fp32 = 128 bytes */                   \
    _Pragma("unroll")                                                          \
    for (int j = 0; j < 4; j++) {                                              \
        const int c_ = j * 256 + tid;                                          \
        const int r_ = c_ >> 3, q_ = c_ & 7;                                   \
        const uint32_t so_ = (uint32_t)(r_ * 128 + ((q_ ^ (r_ & 7)) * 16));    \
        const size_t go_ = (size_t)r_ * 4096 + k0b_ + q_ * 16;                 \
        cp16(sb_ + 0     + so_, pA + go_);                                     \
        cp16(sb_ + 16384 + so_, pB + go_);                                     \
    }                                                                          \
    CP_COMMIT();                                                               \
} while (0)

    float acc[4][4][4];
#pragma unroll
    for (int a = 0; a < 4; a++)
#pragma unroll
        for (int b = 0; b < 4; b++)
#pragma unroll
            for (int c = 0; c < 4; c++) acc[a][b][c] = 0.0f;

    // ldmatrix lane mapping
    const int trow = lane & 7;       // row within 8-row tile
    const int tile = lane >> 3;      // which of 4 tiles this lane addresses
    // A x4 tiles: t0:(r+0,chk0)->a0  t1:(r+8,chk0)->a1  t2:(r+0,chk1)->a2  t3:(r+8,chk1)->a3
    const int a_row_add = trow + (tile & 1) * 8;
    const int a_chk_add = tile >> 1;
    // B x4 tiles: t0:(n+0,chk0)->b0[g0]  t1:(n+0,chk1)->b1[g0]
    //             t2:(n+8,chk0)->b0[g1]  t3:(n+8,chk1)->b1[g1]
    const int b_row_add = trow + (tile >> 1) * 8;
    const int b_chk_add = tile & 1;

    LOAD_STAGE(0, 0);
    LOAD_STAGE(1, 1);

    for (int kt = 0; kt < 32; kt++) {
        if (kt + 1 < 32) CP_WAIT1(); else CP_WAIT0();
        __syncthreads();
        const uint32_t st = sbase + (kt % NSTG) * STG_B;

#pragma unroll
        for (int ks = 0; ks < 4; ks++) {       // k8 steps within BK=32
            const int ckbase = 2 * ks;
            // B fragments: 2 x4 loads cover 4 n8-groups
            uint32_t bfr[2][4];
#pragma unroll
            for (int bi = 0; bi < 2; bi++) {
                const int row = warp_n + bi * 16 + b_row_add;
                const uint32_t q = (uint32_t)((ckbase + b_chk_add) ^ (row & 7));
                ldm_x4(bfr[bi], st + 16384 + (uint32_t)row * 128 + q * 16);
            }
#pragma unroll
            for (int mi = 0; mi < 4; mi++) {
                const int row = warp_m + mi * 16 + a_row_add;
                const uint32_t q = (uint32_t)((ckbase + a_chk_add) ^ (row & 7));
                uint32_t af[4];
                ldm_x4(af, st + (uint32_t)row * 128 + q * 16);
                // af = {a0,a1,a2,a3} -> pass in IDENTITY order
#pragma unroll
                for (int ni = 0; ni < 4; ni++) {
                    uint32_t* bp = &bfr[ni >> 1][(ni & 1) * 2];
                    mma1688(acc[mi][ni], af[0], af[1], af[2], af[3], bp[0], bp[1]);
                }
            }
        }
        __syncthreads();
        if (kt + 2 < 32) LOAD_STAGE(kt + 2, (kt + 2) % NSTG);
    }
#undef LOAD_STAGE

    // epilogue
    const int er = lane >> 2;
    const int ec = (lane & 3) * 2;
#pragma unroll
    for (int mi = 0; mi < 4; mi++) {
        const int row = m_blk + warp_m + mi * 16 + er;
#pragma unroll
        for (int ni = 0; ni < 4; ni++) {
            const int col = n_blk + warp_n + ni * 8 + ec;
            float v0 = acc[mi][ni][0], v1 = acc[mi][ni][1];
            float v2 = acc[mi][ni][2], v3 = acc[mi][ni][3];
            if (col >= sig_start) {
                v0 = 1.0f / (1.0f + expf(-v0));
                v1 = 1.0f / (1.0f + expf(-v1));
                v2 = 1.0f / (1.0f + expf(-v2));
                v3 = 1.0f / (1.0f + expf(-v3));
            }
            float2 lo2 = {v0, v1}, hi2 = {v2, v3};
            *(float2*)&Cc[(size_t)row * ldc + col] = lo2;
            *(float2*)&Cc[(size_t)(row + 8) * ldc + col] = hi2;
        }
    }
}

// ---------------------------------------------------------------------------
// beta = sigmoid(x @ Wbeta^T + bbeta) : (8192, 16)
// ---------------------------------------------------------------------------
__global__ __launch_bounds__(512)
void beta_kernel(const float* __restrict__ x, const float* __restrict__ Wb,
                 const float* __restrict__ bb, float* __restrict__ Beta)
{
    __shared__ float xs[CC];
    const int row = blockIdx.x;
    const int tid = threadIdx.x;
    for (int i = tid; i < CC; i += 512) xs[i] = x[(size_t)row * CC + i];
    __syncthreads();

    const int h = tid >> 5;
    const int lane = tid & 31;
    const float* wrow = &Wb[(size_t)h * CC];
    float acc = 0.0f;
#pragma unroll 8
    for (int c = lane; c < CC; c += 32) acc = fmaf(xs[c], wrow[c], acc);
#pragma unroll
    for (int off = 16; off > 0; off >>= 1)
        acc += __shfl_xor_sync(0xffffffffu, acc, off);
    if (lane == 0) {
        float v = acc + bb[h];
        Beta[(size_t)row * HH + h] = 1.0f / (1.0f + expf(-v));
    }
}

// ---------------------------------------------------------------------------
// L2-normalize Q and K per (row, head) over D=64 (in fused QKVG buffer)
// ---------------------------------------------------------------------------
__global__ __launch_bounds__(256)
void norm_kernel()
{
    const int gw = blockIdx.x * 8 + (threadIdx.x >> 5);
    const int lane = threadIdx.x & 31;
    const int which = gw & 1;                 // 0=Q quarter, 1=K quarter
    const int rem = gw >> 1;
    const int row = rem >> 4;
    const int h = rem & 15;
    float* p = &g_QKVG[(size_t)row * NFUSE + which * CC + h * DD];
    float v0 = p[lane];
    float v1 = p[lane + 32];
    float s = v0 * v0 + v1 * v1;
#pragma unroll
    for (int off = 16; off > 0; off >>= 1)
        s += __shfl_xor_sync(0xffffffffu, s, off);
    float n = sqrtf(s);
    float scale = 1.0f / fmaxf(n, 1e-12f);
    p[lane]      = v0 * scale;
    p[lane + 32] = v1 * scale;
}

// ---------------------------------------------------------------------------
// Delta-rule scan. One block per (b,h). 256 threads.
// Prefetch depth 4, float4 smem reads, dual accumulators, 1 barrier/step.
// Reads fused QKVG (quarters q/k/v/g); writes g_OG = tf32_round(gate*o).
// ---------------------------------------------------------------------------
__global__ __launch_bounds__(256, 1)
void scan_kernel()
{
    const int b = blockIdx.x >> 4;
    const int h = blockIdx.x & 15;
    __shared__ float s[2][256];      // [0:64)q [64:128)k [128:192)v [192:256)g
    __shared__ float sbv[2];

    const int t = threadIdx.x;
    const int d = t >> 2;
    const int cg = t & 3;

    const int arr = t >> 6;          // quarter: 0=q 1=k 2=v 3=g
    const int idx = t & 63;
    const float* src = g_QKVG + (size_t)arr * CC + (size_t)h * DD + idx;
    const size_t rbase = (size_t)b * TT;

    float Mreg[16];
#pragma unroll
    for (int j = 0; j < 16; j++) Mreg[j] = 0.0f;

    float pf0 = src[(rbase + 0) * NFUSE];
    float pf1 = src[(rbase + 1) * NFUSE];
    float pf2 = src[(rbase + 2) * NFUSE];
    float pf3 = src[(rbase + 3) * NFUSE];
    float pb0 = 0, pb1 = 0, pb2 = 0, pb3 = 0;
    if (t == 0) {
        pb0 = g_Beta[(rbase + 0) * HH + h];
        pb1 = g_Beta[(rbase + 1) * HH + h];
        pb2 = g_Beta[(rbase + 2) * HH + h];
        pb3 = g_Beta[(rbase + 3) * HH + h];
    }
    s[0][t] = pf0;
    if (t == 0) sbv[0] = pb0;
    __syncthreads();

#define SCAN_STEP(STEP, BUF, PF_NEXT, PB_NEXT, PF_SELF, PB_SELF)                      \
    {                                                                                 \
        const int ls = ((STEP) + 4 < TT) ? (STEP) + 4 : TT - 1;                       \
        float nv = src[(rbase + ls) * NFUSE];                                         \
        float nb = 0.0f;                                                              \
        if (t == 0) nb = g_Beta[(rbase + ls) * HH + h];                               \
        s[(BUF) ^ 1][t] = PF_NEXT;                                                    \
        if (t == 0) sbv[(BUF) ^ 1] = PB_NEXT;                                         \
        const float4* sq4 = (const float4*)&s[BUF][0];                                \
        const float4* sk4 = (const float4*)&s[BUF][64];                               \
        const float sb = sbv[BUF];                                                    \
        float poA = 0.0f, pkA = 0.0f, poB = 0.0f, pkB = 0.0f;                         \
        float kreg[16];                                                               \
        _Pragma("unroll")                                                             \
        for (int jj = 0; jj < 2; jj++) {                                              \
            float4 qv = sq4[cg * 4 + jj];                                             \
            float4 kv = sk4[cg * 4 + jj];                                             \
            kreg[jj*4+0] = kv.x; kreg[jj*4+1] = kv.y;                                 \
            kreg[jj*4+2] = kv.z; kreg[jj*4+3] = kv.w;                                 \
            poA = fmaf(Mreg[jj*4+0], qv.x, poA); pkA = fmaf(Mreg[jj*4+0], kv.x, pkA); \
            poA = fmaf(Mreg[jj*4+1], qv.y, poA); pkA = fmaf(Mreg[jj*4+1], kv.y, pkA); \
            poA = fmaf(Mreg[jj*4+2], qv.z, poA); pkA = fmaf(Mreg[jj*4+2], kv.z, pkA); \
            poA = fmaf(Mreg[jj*4+3], qv.w, poA); pkA = fmaf(Mreg[jj*4+3], kv.w, pkA); \
        }                                                                             \
        _Pragma("unroll")                                                             \
        for (int jj = 2; jj < 4; jj++) {                                              \
            float4 qv = sq4[cg * 4 + jj];                                             \
            float4 kv = sk4[cg * 4 + jj];                                             \
            kreg[jj*4+0] = kv.x; kreg[jj*4+1] = kv.y;                                 \
            kreg[jj*4+2] = kv.z; kreg[jj*4+3] = kv.w;                                 \
            poB = fmaf(Mreg[jj*4+0], qv.x, poB); pkB = fmaf(Mreg[jj*4+0], kv.x, pkB); \
            poB = fmaf(Mreg[jj*4+1], qv.y, poB); pkB = fmaf(Mreg[jj*4+1], kv.y, pkB); \
            poB = fmaf(Mreg[jj*4+2], qv.z, poB); pkB = fmaf(Mreg[jj*4+2], kv.z, pkB); \
            poB = fmaf(Mreg[jj*4+3], qv.w, poB); pkB = fmaf(Mreg[jj*4+3], kv.w, pkB); \
        }                                                                             \
        float po = poA + poB, pk = pkA + pkB;                                         \
        po += __shfl_xor_sync(0xffffffffu, po, 1);                                    \
        pk += __shfl_xor_sync(0xffffffffu, pk, 1);                                    \
        po += __shfl_xor_sync(0xffffffffu, po, 2);                                    \
        pk += __shfl_xor_sync(0xffffffffu, pk, 2);                                    \
        const float dv = s[BUF][128 + d] - pk;                                        \
        const float bdv = sb * dv;                                                    \
        _Pragma("unroll")                                                             \
        for (int jj = 0; jj < 16; jj++)                                               \
            Mreg[jj] = fmaf(bdv, kreg[jj], Mreg[jj]);                                 \
        if (cg == 0)                                                                  \
            g_OG[(rbase + (STEP)) * CC + h * DD + d] = tf32r(s[BUF][192 + d] * po);   \
        PF_SELF = nv; PB_SELF = nb;                                                   \
        __syncthreads();                                                              \
    }

    for (int st = 0; st < TT; st += 4) {
        SCAN_STEP(st + 0, 0, pf1, pb1, pf0, pb0);
        SCAN_STEP(st + 1, 1, pf2, pb2, pf1, pb1);
        SCAN_STEP(st + 2, 0, pf3, pb3, pf2, pb2);
        SCAN_STEP(st + 3, 1, pf0, pb0, pf3, pb3);
    }
#undef SCAN_STEP
}

// ---------------------------------------------------------------------------
extern "C" void kernel_launch(void* const* d_in, const int* in_sizes, int n_in,
                              void* d_out, int out_size)
{
    const float* x     = (const float*)d_in[0];
    const float* Wq    = (const float*)d_in[1];
    const float* Wk    = (const float*)d_in[2];
    const float* Wv    = (const float*)d_in[3];
    const float* Wbeta = (const float*)d_in[4];
    const float* bbeta = (const float*)d_in[5];
    const float* Wgate = (const float*)d_in[6];
    const float* Wo    = (const float*)d_in[7];
    float* out = (float*)d_out;

    float *QKVGp, *OGp, *Bp, *xtp, *wtp;
    cudaGetSymbolAddress((void**)&QKVGp, g_QKVG);
    cudaGetSymbolAddress((void**)&OGp,   g_OG);
    cudaGetSymbolAddress((void**)&Bp,    g_Beta);
    cudaGetSymbolAddress((void**)&xtp,   g_xt);
    cudaGetSymbolAddress((void**)&wtp,   g_wt);

    cudaFuncSetAttribute(mma_gemm, cudaFuncAttributeMaxDynamicSharedMemorySize, GEMM_SMEM);

    const int WSZ = CC * CC;

    // tf32 pre-rounding (unbiased)
    tf32_round_kernel<<<MROWS * CC / 4 / 256, 256>>>(x, xtp);
    tf32_round_kernel<<<WSZ / 4 / 256, 256>>>(Wq,    wtp + 0 * WSZ);
    tf32_round_kernel<<<WSZ / 4 / 256, 256>>>(Wk,    wtp + 1 * WSZ);
    tf32_round_kernel<<<WSZ / 4 / 256, 256>>>(Wv,    wtp + 2 * WSZ);
    tf32_round_kernel<<<WSZ / 4 / 256, 256>>>(Wgate, wtp + 3 * WSZ);
    tf32_round_kernel<<<WSZ / 4 / 256, 256>>>(Wo,    wtp + 4 * WSZ);

    // fused QKVG projection: N=4096, sigmoid on gate quarter (cols >= 3072)
    dim3 fgrid(NFUSE / 128, MROWS / 128);
    mma_gemm<<<fgrid, 256, GEMM_SMEM>>>(xtp, wtp, QKVGp, NFUSE, 3 * CC);

    beta_kernel<<<MROWS, 512>>>(x, Wbeta, bbeta, Bp);
    norm_kernel<<<(2 * MROWS * HH) / 8, 256>>>();
    scan_kernel<<<BB * HH, 256>>>();

    dim3 ogrid(CC / 128, MROWS / 128);
    mma_gemm<<<ogrid, 256, GEMM_SMEM>>>(OGp, wtp + 4 * WSZ, out, CC, 1 << 30);
}

// round 10
// speedup vs baseline: 3.6383x; 1.0895x over previous
#include <cuda_runtime.h>
#include <cuda_bf16.h>
#include <math.h>
#include <stdint.h>

// Problem dims (fixed)
#define BB 4
#define TT 2048
#define CC 1024
#define HH 16
#define DD 64
#define MROWS (BB*TT)          // 8192
#define NFUSE 4096             // Q|K|V|G fused width

// ---------------------------------------------------------------------------
// Device scratch (cudaMalloc banned)
// ---------------------------------------------------------------------------
__device__ float g_QKVG[MROWS*NFUSE];     // fused Q|K|V|G, row stride 4096
__device__ float g_OG[MROWS*CC];          // tf32-rounded gate*o
__device__ float g_Beta[MROWS*HH];
__device__ float g_xt[MROWS*CC];          // tf32-rounded x
__device__ float g_wt[5*CC*CC];           // tf32-rounded Wq|Wk|Wv|Wgate|Wo

// ---------------------------------------------------------------------------
// PTX helpers (base-ISA only: mma.sync / ldmatrix / cp.async / cvt.tf32)
// ---------------------------------------------------------------------------
__device__ __forceinline__ uint32_t smem_u32(const void* p) {
    uint32_t a;
    asm("{ .reg .u64 t; cvta.to.shared.u64 t, %1; cvt.u32.u64 %0, t; }" : "=r"(a) : "l"(p));
    return a;
}
__device__ __forceinline__ void cp16(uint32_t dst, const void* src) {
    asm volatile("cp.async.cg.shared.global [%0], [%1], 16;" :: "r"(dst), "l"(src));
}
#define CP_COMMIT() asm volatile("cp.async.commit_group;" ::: "memory")
#define CP_WAIT1()  asm volatile("cp.async.wait_group 1;" ::: "memory")
#define CP_WAIT0()  asm volatile("cp.async.wait_group 0;" ::: "memory")

__device__ __forceinline__ void ldm_x4(uint32_t* r, uint32_t addr) {
    asm volatile("ldmatrix.sync.aligned.m8n8.x4.shared.b16 {%0,%1,%2,%3}, [%4];"
        : "=r"(r[0]), "=r"(r[1]), "=r"(r[2]), "=r"(r[3]) : "r"(addr));
}
// tf32 mma: D += A*B, A: 4 regs (a0..a3), B: 2 regs
__device__ __forceinline__ void mma1688(float* d, uint32_t a0, uint32_t a1,
                                        uint32_t a2, uint32_t a3,
                                        uint32_t b0, uint32_t b1) {
    asm volatile("mma.sync.aligned.m16n8k8.row.col.f32.tf32.tf32.f32 "
        "{%0,%1,%2,%3}, {%4,%5,%6,%7}, {%8,%9}, {%0,%1,%2,%3};"
        : "+f"(d[0]), "+f"(d[1]), "+f"(d[2]), "+f"(d[3])
        : "r"(a0), "r"(a1), "r"(a2), "r"(a3), "r"(b0), "r"(b1));
}
__device__ __forceinline__ float tf32r(float x) {
    float r;
    asm("cvt.rna.tf32.f32 %0, %1;" : "=f"(r) : "f"(x));
    return r;
}

// ---------------------------------------------------------------------------
// fp32 -> tf32-rounded fp32 (unbiased), float4-vectorized
// ---------------------------------------------------------------------------
__global__ __launch_bounds__(256)
void tf32_round_kernel(const float* __restrict__ in, float* __restrict__ out)
{
    const int i = blockIdx.x * 256 + threadIdx.x;
    float4 v = ((const float4*)in)[i];
    v.x = tf32r(v.x); v.y = tf32r(v.y); v.z = tf32r(v.z); v.w = tf32r(v.w);
    ((float4*)out)[i] = v;
}

// all five weights in one launch; blockIdx selects source
__global__ __launch_bounds__(256)
void wround_kernel(const float* __restrict__ w0, const float* __restrict__ w1,
                   const float* __restrict__ w2, const float* __restrict__ w3,
                   const float* __restrict__ w4, float* __restrict__ out)
{
    const int i = blockIdx.x * 256 + threadIdx.x;       // float4 index, 5*WSZ/4
    const int per = (CC * CC) / 4;                      // 262144
    const int which = i / per;
    const int local = i - which * per;
    const float* src = (which == 0) ? w0 : (which == 1) ? w1 :
                       (which == 2) ? w2 : (which == 3) ? w3 : w4;
    float4 v = ((const float4*)src)[local];
    v.x = tf32r(v.x); v.y = tf32r(v.y); v.z = tf32r(v.z); v.w = tf32r(v.w);
    ((float4*)out)[i] = v;
}

// ---------------------------------------------------------------------------
// TF32 HMMA GEMM: C[8192,N] = A[8192,1024] @ B[N,1024]^T  (fp32 in/out)
// CTA tile 128x128, BK=32, 3-stage cp.async, 96KB smem -> 2 CTAs/SM.
// (unchanged from Round 8 — verified passing)
// ---------------------------------------------------------------------------
#define STG_B 32768
#define NSTG  3
#define GEMM_SMEM (NSTG*STG_B)   // 96 KB

__global__ __launch_bounds__(256, 2)
void mma_gemm(const float* __restrict__ Ag, const float* __restrict__ Bg,
              float* __restrict__ Cc, int ldc, int sig_start)
{
    extern __shared__ char smem[];
    const uint32_t sbase = smem_u32(smem);
    const int tid = threadIdx.x;
    const int lane = tid & 31;
    const int wid = tid >> 5;
    const int m_blk = blockIdx.y * 128;
    const int n_blk = blockIdx.x * 128;
    const int warp_m = (wid >> 2) * 64;
    const int warp_n = (wid & 3) * 32;

    const char* pA = (const char*)(Ag + (size_t)m_blk * CC);
    const char* pB = (const char*)(Bg + (size_t)n_blk * CC);

#define LOAD_STAGE(KT, STG) do {                                               \
    const uint32_t sb_ = sbase + (STG) * STG_B;                                \
    const int k0b_ = (KT) * 128;                                               \
    _Pragma("unroll")                                                          \
    for (int j = 0; j < 4; j++) {                                              \
        const int c_ = j * 256 + tid;                                          \
        const int r_ = c_ >> 3, q_ = c_ & 7;                                   \
        const uint32_t so_ = (uint32_t)(r_ * 128 + ((q_ ^ (r_ & 7)) * 16));    \
        const size_t go_ = (size_t)r_ * 4096 + k0b_ + q_ * 16;                 \
        cp16(sb_ + 0     + so_, pA + go_);                                     \
        cp16(sb_ + 16384 + so_, pB + go_);                                     \
    }                                                                          \
    CP_COMMIT();                                                               \
} while (0)

    float acc[4][4][4];
#pragma unroll
    for (int a = 0; a < 4; a++)
#pragma unroll
        for (int b = 0; b < 4; b++)
#pragma unroll
            for (int c = 0; c < 4; c++) acc[a][b][c] = 0.0f;

    const int trow = lane & 7;
    const int tile = lane >> 3;
    const int a_row_add = trow + (tile & 1) * 8;
    const int a_chk_add = tile >> 1;
    const int b_row_add = trow + (tile >> 1) * 8;
    const int b_chk_add = tile & 1;

    LOAD_STAGE(0, 0);
    LOAD_STAGE(1, 1);

    for (int kt = 0; kt < 32; kt++) {
        if (kt + 1 < 32) CP_WAIT1(); else CP_WAIT0();
        __syncthreads();
        const uint32_t st = sbase + (kt % NSTG) * STG_B;

#pragma unroll
        for (int ks = 0; ks < 4; ks++) {
            const int ckbase = 2 * ks;
            uint32_t bfr[2][4];
#pragma unroll
            for (int bi = 0; bi < 2; bi++) {
                const int row = warp_n + bi * 16 + b_row_add;
                const uint32_t q = (uint32_t)((ckbase + b_chk_add) ^ (row & 7));
                ldm_x4(bfr[bi], st + 16384 + (uint32_t)row * 128 + q * 16);
            }
#pragma unroll
            for (int mi = 0; mi < 4; mi++) {
                const int row = warp_m + mi * 16 + a_row_add;
                const uint32_t q = (uint32_t)((ckbase + a_chk_add) ^ (row & 7));
                uint32_t af[4];
                ldm_x4(af, st + (uint32_t)row * 128 + q * 16);
#pragma unroll
                for (int ni = 0; ni < 4; ni++) {
                    uint32_t* bp = &bfr[ni >> 1][(ni & 1) * 2];
                    mma1688(acc[mi][ni], af[0], af[1], af[2], af[3], bp[0], bp[1]);
                }
            }
        }
        __syncthreads();
        if (kt + 2 < 32) LOAD_STAGE(kt + 2, (kt + 2) % NSTG);
    }
#undef LOAD_STAGE

    const int er = lane >> 2;
    const int ec = (lane & 3) * 2;
#pragma unroll
    for (int mi = 0; mi < 4; mi++) {
        const int row = m_blk + warp_m + mi * 16 + er;
#pragma unroll
        for (int ni = 0; ni < 4; ni++) {
            const int col = n_blk + warp_n + ni * 8 + ec;
            float v0 = acc[mi][ni][0], v1 = acc[mi][ni][1];
            float v2 = acc[mi][ni][2], v3 = acc[mi][ni][3];
            if (col >= sig_start) {
                v0 = 1.0f / (1.0f + expf(-v0));
                v1 = 1.0f / (1.0f + expf(-v1));
                v2 = 1.0f / (1.0f + expf(-v2));
                v3 = 1.0f / (1.0f + expf(-v3));
            }
            float2 lo2 = {v0, v1}, hi2 = {v2, v3};
            *(float2*)&Cc[(size_t)row * ldc + col] = lo2;
            *(float2*)&Cc[(size_t)(row + 8) * ldc + col] = hi2;
        }
    }
}

// ---------------------------------------------------------------------------
// beta = sigmoid(x @ Wbeta^T + bbeta) : (8192, 16)
// ---------------------------------------------------------------------------
__global__ __launch_bounds__(512)
void beta_kernel(const float* __restrict__ x, const float* __restrict__ Wb,
                 const float* __restrict__ bb, float* __restrict__ Beta)
{
    __shared__ float xs[CC];
    const int row = blockIdx.x;
    const int tid = threadIdx.x;
    for (int i = tid; i < CC; i += 512) xs[i] = x[(size_t)row * CC + i];
    __syncthreads();

    const int h = tid >> 5;
    const int lane = tid & 31;
    const float* wrow = &Wb[(size_t)h * CC];
    float acc = 0.0f;
#pragma unroll 8
    for (int c = lane; c < CC; c += 32) acc = fmaf(xs[c], wrow[c], acc);
#pragma unroll
    for (int off = 16; off > 0; off >>= 1)
        acc += __shfl_xor_sync(0xffffffffu, acc, off);
    if (lane == 0) {
        float v = acc + bb[h];
        Beta[(size_t)row * HH + h] = 1.0f / (1.0f + expf(-v));
    }
}

// ---------------------------------------------------------------------------
// L2-normalize Q and K per (row, head) over D=64 (in fused QKVG buffer)
// ---------------------------------------------------------------------------
__global__ __launch_bounds__(256)
void norm_kernel()
{
    const int gw = blockIdx.x * 8 + (threadIdx.x >> 5);
    const int lane = threadIdx.x & 31;
    const int which = gw & 1;
    const int rem = gw >> 1;
    const int row = rem >> 4;
    const int h = rem & 15;
    float* p = &g_QKVG[(size_t)row * NFUSE + which * CC + h * DD];
    float v0 = p[lane];
    float v1 = p[lane + 32];
    float s = v0 * v0 + v1 * v1;
#pragma unroll
    for (int off = 16; off > 0; off >>= 1)
        s += __shfl_xor_sync(0xffffffffu, s, off);
    float n = sqrtf(s);
    float scale = 1.0f / fmaxf(n, 1e-12f);
    p[lane]      = v0 * scale;
    p[lane + 32] = v1 * scale;
}

// ---------------------------------------------------------------------------
// Delta-rule scan. One block per (b,h). 256 threads.
// Window = 2 steps, ONE barrier per window, 4 smem buffers (read/write sets
// disjoint mod 4). 4-pair register queue: LDG -> STS distance = 3 windows
// (6 steps ~ 1000+ cyc) -> DRAM latency fully covered.
// ---------------------------------------------------------------------------
__global__ __launch_bounds__(256, 1)
void scan_kernel()
{
    const int b = blockIdx.x >> 4;
    const int h = blockIdx.x & 15;
    __shared__ float s[4][256];      // per buf: [0:64)q [64:128)k [128:192)v [192:256)g
    __shared__ float sbv[4];

    const int t = threadIdx.x;
    const int d = t >> 2;
    const int cg = t & 3;
    const int arr = t >> 6;          // quarter: 0=q 1=k 2=v 3=g
    const int idx = t & 63;
    const float* src = g_QKVG + (size_t)arr * CC + (size_t)h * DD + idx;
    const size_t rbase = (size_t)b * TT;

    float Mreg[16];
#pragma unroll
    for (int j = 0; j < 16; j++) Mreg[j] = 0.0f;

    // register queue slots 0..3 hold pairs 0..3 (steps 0..7)
    float f0a = src[(rbase + 0) * NFUSE], f0b = src[(rbase + 1) * NFUSE];
    float f1a = src[(rbase + 2) * NFUSE], f1b = src[(rbase + 3) * NFUSE];
    float f2a = src[(rbase + 4) * NFUSE], f2b = src[(rbase + 5) * NFUSE];
    float f3a = src[(rbase + 6) * NFUSE], f3b = src[(rbase + 7) * NFUSE];
    float b0a = 0, b0b = 0, b1a = 0, b1b = 0, b2a = 0, b2b = 0, b3a = 0, b3b = 0;
    if (t == 0) {
        b0a = g_Beta[(rbase + 0) * HH + h]; b0b = g_Beta[(rbase + 1) * HH + h];
        b1a = g_Beta[(rbase + 2) * HH + h]; b1b = g_Beta[(rbase + 3) * HH + h];
        b2a = g_Beta[(rbase + 4) * HH + h]; b2b = g_Beta[(rbase + 5) * HH + h];
        b3a = g_Beta[(rbase + 6) * HH + h]; b3b = g_Beta[(rbase + 7) * HH + h];
    }
    s[0][t] = f0a; s[1][t] = f0b;
    if (t == 0) { sbv[0] = b0a; sbv[1] = b0b; }
    __syncthreads();

    // one scan step: read buffer RB, update M, write gated output
#define SCAN_STEP(STEP, RB)                                                           \
    {                                                                                 \
        const float4* sq4 = (const float4*)&s[RB][0];                                 \
        const float4* sk4 = (const float4*)&s[RB][64];                                \
        const float sb = sbv[RB];                                                     \
        float poA = 0.0f, pkA = 0.0f, poB = 0.0f, pkB = 0.0f;                         \
        float kreg[16];                                                               \
        _Pragma("unroll")                                                             \
        for (int jj = 0; jj < 2; jj++) {                                              \
            float4 qv = sq4[cg * 4 + jj];                                             \
            float4 kv = sk4[cg * 4 + jj];                                             \
            kreg[jj*4+0] = kv.x; kreg[jj*4+1] = kv.y;                                 \
            kreg[jj*4+2] = kv.z; kreg[jj*4+3] = kv.w;                                 \
            poA = fmaf(Mreg[jj*4+0], qv.x, poA); pkA = fmaf(Mreg[jj*4+0], kv.x, pkA); \
            poA = fmaf(Mreg[jj*4+1], qv.y, poA); pkA = fmaf(Mreg[jj*4+1], kv.y, pkA); \
            poA = fmaf(Mreg[jj*4+2], qv.z, poA); pkA = fmaf(Mreg[jj*4+2], kv.z, pkA); \
            poA = fmaf(Mreg[jj*4+3], qv.w, poA); pkA = fmaf(Mreg[jj*4+3], kv.w, pkA); \
        }                                                                             \
        _Pragma("unroll")                                                             \
        for (int jj = 2; jj < 4; jj++) {                                              \
            float4 qv = sq4[cg * 4 + jj];                                             \
            float4 kv = sk4[cg * 4 + jj];                                             \
            kreg[jj*4+0] = kv.x; kreg[jj*4+1] = kv.y;                                 \
            kreg[jj*4+2] = kv.z; kreg[jj*4+3] = kv.w;                                 \
            poB = fmaf(Mreg[jj*4+0], qv.x, poB); pkB = fmaf(Mreg[jj*4+0], kv.x, pkB); \
            poB = fmaf(Mreg[jj*4+1], qv.y, poB); pkB = fmaf(Mreg[jj*4+1], kv.y, pkB); \
            poB = fmaf(Mreg[jj*4+2], qv.z, poB); pkB = fmaf(Mreg[jj*4+2], kv.z, pkB); \
            poB = fmaf(Mreg[jj*4+3], qv.w, poB); pkB = fmaf(Mreg[jj*4+3], kv.w, pkB); \
        }                                                                             \
        float po = poA + poB, pk = pkA + pkB;                                         \
        po += __shfl_xor_sync(0xffffffffu, po, 1);                                    \
        pk += __shfl_xor_sync(0xffffffffu, pk, 1);                                    \
        po += __shfl_xor_sync(0xffffffffu, po, 2);                                    \
        pk += __shfl_xor_sync(0xffffffffu, pk, 2);                                    \
        const float dv = s[RB][128 + d] - pk;                                         \
        const float bdv = sb * dv;                                                    \
        _Pragma("unroll")                                                             \
        for (int jj = 0; jj < 16; jj++)                                               \
            Mreg[jj] = fmaf(bdv, kreg[jj], Mreg[jj]);                                 \
        if (cg == 0)                                                                  \
            g_OG[(rbase + (STEP)) * CC + h * DD + d] = tf32r(s[RB][192 + d] * po);    \
    }

    // window j: LDG pair j+4 -> slot j&3; STS pair j+1 (slot (j+1)&3) -> bufs WB;
    // compute steps 2j (buf RB0), 2j+1 (buf RB1); one barrier.
#define WINDOW(J, RB0, RB1, WB0, WB1, SFA, SFB, SBA, SBB, LFA, LFB, LBA, LBB)         \
    {                                                                                 \
        int ls = 2 * (J) + 8; if (ls > TT - 2) ls = TT - 2;                           \
        LFA = src[(rbase + ls) * NFUSE];                                              \
        LFB = src[(rbase + ls + 1) * NFUSE];                                          \
        if (t == 0) {                                                                 \
            LBA = g_Beta[(rbase + ls) * HH + h];                                      \
            LBB = g_Beta[(rbase + ls + 1) * HH + h];                                  \
        }                                                                             \
        s[WB0][t] = SFA; s[WB1][t] = SFB;                                             \
        if (t == 0) { sbv[WB0] = SBA; sbv[WB1] = SBB; }                               \
        SCAN_STEP(2 * (J),     RB0);                                                  \
        SCAN_STEP(2 * (J) + 1, RB1);                                                  \
        __syncthreads();                                                              \
    }

    for (int m = 0; m < TT / 8; m++) {
        const int j0 = 4 * m;
        WINDOW(j0 + 0, 0, 1, 2, 3, f1a, f1b, b1a, b1b, f0a, f0b, b0a, b0b);
        WINDOW(j0 + 1, 2, 3, 0, 1, f2a, f2b, b2a, b2b, f1a, f1b, b1a, b1b);
        WINDOW(j0 + 2, 0, 1, 2, 3, f3a, f3b, b3a, b3b, f2a, f2b, b2a, b2b);
        WINDOW(j0 + 3, 2, 3, 0, 1, f0a, f0b, b0a, b0b, f3a, f3b, b3a, b3b);
    }
#undef WINDOW
#undef SCAN_STEP
}

// ---------------------------------------------------------------------------
extern "C" void kernel_launch(void* const* d_in, const int* in_sizes, int n_in,
                              void* d_out, int out_size)
{
    const float* x     = (const float*)d_in[0];
    const float* Wq    = (const float*)d_in[1];
    const float* Wk    = (const float*)d_in[2];
    const float* Wv    = (const float*)d_in[3];
    const float* Wbeta = (const float*)d_in[4];
    const float* bbeta = (const float*)d_in[5];
    const float* Wgate = (const float*)d_in[6];
    const float* Wo    = (const float*)d_in[7];
    float* out = (float*)d_out;

    float *QKVGp, *OGp, *Bp, *xtp, *wtp;
    cudaGetSymbolAddress((void**)&QKVGp, g_QKVG);
    cudaGetSymbolAddress((void**)&OGp,   g_OG);
    cudaGetSymbolAddress((void**)&Bp,    g_Beta);
    cudaGetSymbolAddress((void**)&xtp,   g_xt);
    cudaGetSymbolAddress((void**)&wtp,   g_wt);

    cudaFuncSetAttribute(mma_gemm, cudaFuncAttributeMaxDynamicSharedMemorySize, GEMM_SMEM);

    const int WSZ = CC * CC;

    // tf32 pre-rounding (unbiased)
    tf32_round_kernel<<<MROWS * CC / 4 / 256, 256>>>(x, xtp);
    wround_kernel<<<5 * WSZ / 4 / 256, 256>>>(Wq, Wk, Wv, Wgate, Wo, wtp);

    // fused QKVG projection: N=4096, sigmoid on gate quarter (cols >= 3072)
    dim3 fgrid(NFUSE / 128, MROWS / 128);
    mma_gemm<<<fgrid, 256, GEMM_SMEM>>>(xtp, wtp, QKVGp, NFUSE, 3 * CC);

    beta_kernel<<<MROWS, 512>>>(x, Wbeta, bbeta, Bp);
    norm_kernel<<<(2 * MROWS * HH) / 8, 256>>>();
    scan_kernel<<<BB * HH, 256>>>();

    dim3 ogrid(CC / 128, MROWS / 128);
    mma_gemm<<<ogrid, 256, GEMM_SMEM>>>(OGp, wtp + 4 * WSZ, out, CC, 1 << 30);
}